// round 1
// baseline (speedup 1.0000x reference)
#include <cuda_runtime.h>
#include <math.h>

// Problem shape (fixed by the reference)
#define BB 4
#define TT 2048
#define EE 768
#define HH 8
#define HE 6144          // H*E
#define MR 8192          // B*T

// Scratch (allocation-free rule -> __device__ globals)
__device__ float g_q[(size_t)MR * HE];
__device__ float g_k[(size_t)MR * HE];
__device__ float g_v[(size_t)MR * HE];
__device__ float g_att[(size_t)BB * HH * (size_t)TT * TT];
__device__ float g_ho[(size_t)MR * HE];

// ---------------------------------------------------------------------------
// Generic fp32 SGEMM: C = alpha * A @ B(^T) (+ bias), row-major, batched via
// two-level (batch, head) strides. All dims assumed divisible by tile sizes.
// BM=BN=128, BK=8, TM=TN=8, 256 threads.
// ---------------------------------------------------------------------------
template<bool TRANSB, bool BIAS>
__global__ __launch_bounds__(256)
void sgemm_kernel(const float* __restrict__ A, const float* __restrict__ B,
                  const float* __restrict__ bias, float* __restrict__ C,
                  int M, int N, int K, int lda, int ldb, int ldc,
                  int nh, long sAb, long sAh, long sBb, long sBh,
                  long sCb, long sCh, float alpha)
{
    const int BM = 128, BN = 128, BK = 8, TM = 8, TN = 8;
    __shared__ float As[BK][BM + 4];
    __shared__ float Bs[BK][BN + 4];

    const int bz = blockIdx.z;
    const int bb = bz / nh;
    const int hh = bz - bb * nh;
    A += (long)bb * sAb + (long)hh * sAh;
    B += (long)bb * sBb + (long)hh * sBh;
    C += (long)bb * sCb + (long)hh * sCh;

    const int tid = threadIdx.x;
    const int tx = tid & 15;        // 16 threads along N
    const int ty = tid >> 4;        // 16 threads along M
    const int row0 = blockIdx.y * BM;
    const int col0 = blockIdx.x * BN;

    float acc[TM][TN] = {};

    for (int k0 = 0; k0 < K; k0 += BK) {
        // Load A tile (128x8) -> As[k][m]
        #pragma unroll
        for (int i = tid; i < BM * BK; i += 256) {
            int m = i >> 3, kk = i & 7;
            As[kk][m] = A[(size_t)(row0 + m) * lda + (k0 + kk)];
        }
        // Load B tile -> Bs[k][n]
        if (TRANSB) {
            #pragma unroll
            for (int i = tid; i < BN * BK; i += 256) {
                int n = i >> 3, kk = i & 7;
                Bs[kk][n] = B[(size_t)(col0 + n) * ldb + (k0 + kk)];
            }
        } else {
            #pragma unroll
            for (int i = tid; i < BK * BN; i += 256) {
                int kk = i >> 7, n = i & 127;
                Bs[kk][n] = B[(size_t)(k0 + kk) * ldb + (col0 + n)];
            }
        }
        __syncthreads();

        #pragma unroll
        for (int kk = 0; kk < BK; kk++) {
            // float4 smem reads: conflict-free with the +4 pad
            float4 a0 = *reinterpret_cast<const float4*>(&As[kk][ty * TM]);
            float4 a1 = *reinterpret_cast<const float4*>(&As[kk][ty * TM + 4]);
            float4 b0 = *reinterpret_cast<const float4*>(&Bs[kk][tx * TN]);
            float4 b1 = *reinterpret_cast<const float4*>(&Bs[kk][tx * TN + 4]);
            float ra[TM] = {a0.x, a0.y, a0.z, a0.w, a1.x, a1.y, a1.z, a1.w};
            float rb[TN] = {b0.x, b0.y, b0.z, b0.w, b1.x, b1.y, b1.z, b1.w};
            #pragma unroll
            for (int i = 0; i < TM; i++)
                #pragma unroll
                for (int j = 0; j < TN; j++)
                    acc[i][j] = fmaf(ra[i], rb[j], acc[i][j]);
        }
        __syncthreads();
    }

    #pragma unroll
    for (int i = 0; i < TM; i++) {
        int r = row0 + ty * TM + i;
        #pragma unroll
        for (int j = 0; j < TN; j++) {
            int c = col0 + tx * TN + j;
            float v = alpha * acc[i][j];
            if (BIAS) v += bias[c];
            C[(size_t)r * ldc + c] = v;
        }
    }
}

// ---------------------------------------------------------------------------
// Row softmax over rows of length TT. One block (256 thr) per row,
// 8 values per thread kept in registers.
// ---------------------------------------------------------------------------
__global__ __launch_bounds__(256)
void softmax_kernel(float* __restrict__ att)
{
    float* row = att + (size_t)blockIdx.x * TT;
    const int tid = threadIdx.x;
    float v[8];
    float mx = -1e30f;
    #pragma unroll
    for (int i = 0; i < 8; i++) {
        v[i] = row[tid + (i << 8)];
        mx = fmaxf(mx, v[i]);
    }
    __shared__ float red[32];
    // block max
    #pragma unroll
    for (int o = 16; o > 0; o >>= 1)
        mx = fmaxf(mx, __shfl_xor_sync(0xffffffffu, mx, o));
    if ((tid & 31) == 0) red[tid >> 5] = mx;
    __syncthreads();
    if (tid < 32) {
        float m2 = (tid < 8) ? red[tid] : -1e30f;
        #pragma unroll
        for (int o = 4; o > 0; o >>= 1)
            m2 = fmaxf(m2, __shfl_xor_sync(0xffffffffu, m2, o));
        if (tid == 0) red[0] = m2;
    }
    __syncthreads();
    mx = red[0];
    __syncthreads();   // everyone has read red[0] before it is reused

    float s = 0.f;
    #pragma unroll
    for (int i = 0; i < 8; i++) {
        v[i] = __expf(v[i] - mx);
        s += v[i];
    }
    #pragma unroll
    for (int o = 16; o > 0; o >>= 1)
        s += __shfl_xor_sync(0xffffffffu, s, o);
    if ((tid & 31) == 0) red[tid >> 5] = s;
    __syncthreads();
    if (tid < 32) {
        float s2 = (tid < 8) ? red[tid] : 0.f;
        #pragma unroll
        for (int o = 4; o > 0; o >>= 1)
            s2 += __shfl_xor_sync(0xffffffffu, s2, o);
        if (tid == 0) red[0] = s2;
    }
    __syncthreads();
    const float inv = 1.f / red[0];
    #pragma unroll
    for (int i = 0; i < 8; i++)
        row[tid + (i << 8)] = v[i] * inv;
}

// ---------------------------------------------------------------------------
extern "C" void kernel_launch(void* const* d_in, const int* in_sizes, int n_in,
                              void* d_out, int out_size)
{
    const float* x  = (const float*)d_in[0];   // [4,2048,768]
    const float* Wq = (const float*)d_in[1];   // [768,6144]
    const float* Wk = (const float*)d_in[2];
    const float* Wv = (const float*)d_in[3];
    const float* Wu = (const float*)d_in[4];   // [6144,768]
    const float* bu = (const float*)d_in[5];   // [768]
    float* out = (float*)d_out;                // [8192,768]

    float *q, *k, *v, *att, *ho;
    cudaGetSymbolAddress((void**)&q,   g_q);
    cudaGetSymbolAddress((void**)&k,   g_k);
    cudaGetSymbolAddress((void**)&v,   g_v);
    cudaGetSymbolAddress((void**)&att, g_att);
    cudaGetSymbolAddress((void**)&ho,  g_ho);

    const dim3 blk(256);
    const float alpha_scores = 1.0f / sqrtf((float)EE);

    // 1) QKV projections: [8192,768]@[768,6144]
    {
        dim3 g(HE / 128, MR / 128, 1);
        sgemm_kernel<false, false><<<g, blk>>>(x, Wq, nullptr, q,
            MR, HE, EE, EE, HE, HE, 1, 0, 0, 0, 0, 0, 0, 1.f);
        sgemm_kernel<false, false><<<g, blk>>>(x, Wk, nullptr, k,
            MR, HE, EE, EE, HE, HE, 1, 0, 0, 0, 0, 0, 0, 1.f);
        sgemm_kernel<false, false><<<g, blk>>>(x, Wv, nullptr, v,
            MR, HE, EE, EE, HE, HE, 1, 0, 0, 0, 0, 0, 0, 1.f);
    }

    // 2) scores: per (b,h)  S = alpha * q_bh @ k_bh^T   [2048x2048]
    {
        dim3 g(TT / 128, TT / 128, BB * HH);
        sgemm_kernel<true, false><<<g, blk>>>(q, k, nullptr, att,
            TT, TT, EE, HE, HE, TT,
            HH,
            (long)TT * HE, (long)EE,            // A = q
            (long)TT * HE, (long)EE,            // B = k
            (long)HH * TT * TT, (long)TT * TT,  // C = att
            alpha_scores);
    }

    // 3) softmax over rows
    softmax_kernel<<<BB * HH * TT, blk>>>(att);

    // 4) O = att @ v_bh   [2048x2048]@[2048x768] -> ho (layout b,t,h,e)
    {
        dim3 g(EE / 128, TT / 128, BB * HH);
        sgemm_kernel<false, false><<<g, blk>>>(att, v, nullptr, ho,
            TT, EE, TT, TT, HE, HE,
            HH,
            (long)HH * TT * TT, (long)TT * TT,  // A = att
            (long)TT * HE, (long)EE,            // B = v
            (long)TT * HE, (long)EE,            // C = ho
            1.f);
    }

    // 5) output projection + bias: [8192,6144]@[6144,768] + bu
    {
        dim3 g(EE / 128, MR / 128, 1);
        sgemm_kernel<false, true><<<g, blk>>>(ho, Wu, bu, out,
            MR, EE, HE, HE, EE, EE, 1, 0, 0, 0, 0, 0, 0, 1.f);
    }
}

// round 2
// speedup vs baseline: 3.1096x; 3.1096x over previous
#include <cuda_runtime.h>
#include <math.h>
#include <stdint.h>

// Problem shape (fixed by the reference)
#define BB 4
#define TT 2048
#define EE 768
#define HH 8
#define HE 6144          // H*E
#define MR 8192          // B*T

// Scratch (allocation-free rule -> __device__ globals)
__device__ float g_q[(size_t)MR * HE];
__device__ float g_k[(size_t)MR * HE];
__device__ float g_v[(size_t)MR * HE];
__device__ float g_att[(size_t)BB * HH * (size_t)TT * TT];
__device__ float g_ho[(size_t)MR * HE];

// Tiling
#define BM 128
#define BN 128
#define BK 32
#define AS_STRIDE 36      // BK + 4  (bank-conflict-free fragment reads)
#define BS_STRIDE 136     // BN + 8
#define BT_STRIDE 36      // BK + 4
#define AS_BUF (BM * AS_STRIDE)            // 4608 floats per buffer

__device__ __forceinline__ uint32_t f2tf32(float f) {
    uint32_t u;
    asm("cvt.rna.tf32.f32 %0, %1;" : "=r"(u) : "f"(f));
    return u;
}
__device__ __forceinline__ void cp_async16(void* smem_dst, const void* gmem_src) {
    uint32_t s = (uint32_t)__cvta_generic_to_shared(smem_dst);
    asm volatile("cp.async.cg.shared.global [%0], [%1], 16;" :: "r"(s), "l"(gmem_src));
}
__device__ __forceinline__ void cp_commit() { asm volatile("cp.async.commit_group;" ::: "memory"); }
template<int N>
__device__ __forceinline__ void cp_wait() { asm volatile("cp.async.wait_group %0;" :: "n"(N) : "memory"); }

// ---------------------------------------------------------------------------
// tf32 tensor-core GEMM: C = alpha * A @ B(^T) (+ bias), row-major, batched
// via (batch, head) strides. All dims divisible by tile sizes (true here).
// ---------------------------------------------------------------------------
template<bool TRANSB, bool BIAS>
__global__ __launch_bounds__(256, 1)
void tgemm(const float* __restrict__ A, const float* __restrict__ B,
           const float* __restrict__ bias, float* __restrict__ C,
           int M, int N, int K, int lda, int ldb, int ldc,
           int nh, long sAb, long sAh, long sBb, long sBh,
           long sCb, long sCh, float alpha)
{
    extern __shared__ float smem[];
    float* As = smem;                                  // 2 buffers
    float* Bs = smem + 2 * AS_BUF;
    const int BSZ = TRANSB ? (BN * BT_STRIDE) : (BK * BS_STRIDE);

    const int bz = blockIdx.z;
    const int bb = bz / nh;
    const int hh = bz - bb * nh;
    A += (long)bb * sAb + (long)hh * sAh;
    B += (long)bb * sBb + (long)hh * sBh;
    C += (long)bb * sCb + (long)hh * sCh;

    const int tid  = threadIdx.x;
    const int warp = tid >> 5, lane = tid & 31;
    const int g    = lane >> 2, tig = lane & 3;
    const int wm   = (warp >> 2) * 64;   // 2 warps along M
    const int wn   = (warp & 3)  * 32;   // 4 warps along N
    const int row0 = blockIdx.y * BM;
    const int col0 = blockIdx.x * BN;

    float acc[4][4][4] = {};  // [mi][ni][reg]

    // Loader index decompositions (all in-bounds; dims divide tiles exactly)
    const int a_m  = tid >> 3, a_k4 = (tid & 7) << 2;       // A: 4 passes, m += 32
    const int bn_k = tid >> 5, bn_n4 = (tid & 31) << 2;     // B normal: 4 passes, k += 8
    const int bt_n = tid >> 3, bt_k4 = (tid & 7) << 2;      // B trans:  4 passes, n += 32

    #define LOAD_TILE(K0, BUF)                                                        \
    {                                                                                 \
        float* as_ = As + (BUF) * AS_BUF;                                             \
        _Pragma("unroll")                                                             \
        for (int p = 0; p < 4; p++) {                                                 \
            int m = a_m + p * 32;                                                     \
            cp_async16(&as_[m * AS_STRIDE + a_k4],                                    \
                       &A[(size_t)(row0 + m) * lda + (K0) + a_k4]);                   \
        }                                                                             \
        float* bs_ = Bs + (BUF) * BSZ;                                                \
        if (TRANSB) {                                                                 \
            _Pragma("unroll")                                                         \
            for (int p = 0; p < 4; p++) {                                             \
                int n = bt_n + p * 32;                                                \
                cp_async16(&bs_[n * BT_STRIDE + bt_k4],                               \
                           &B[(size_t)(col0 + n) * ldb + (K0) + bt_k4]);              \
            }                                                                         \
        } else {                                                                      \
            _Pragma("unroll")                                                         \
            for (int p = 0; p < 4; p++) {                                             \
                int kk = bn_k + p * 8;                                                \
                cp_async16(&bs_[kk * BS_STRIDE + bn_n4],                              \
                           &B[(size_t)((K0) + kk) * ldb + col0 + bn_n4]);             \
            }                                                                         \
        }                                                                             \
        cp_commit();                                                                  \
    }

    LOAD_TILE(0, 0);
    const int ntiles = K / BK;

    for (int kt = 0; kt < ntiles; kt++) {
        const int buf = kt & 1;
        if (kt + 1 < ntiles) {
            LOAD_TILE((kt + 1) * BK, buf ^ 1);
            cp_wait<1>();
        } else {
            cp_wait<0>();
        }
        __syncthreads();

        const float* as = As + buf * AS_BUF;
        const float* bs = Bs + buf * BSZ;

        #pragma unroll
        for (int kf = 0; kf < 4; kf++) {
            uint32_t af[4][4];
            #pragma unroll
            for (int mi = 0; mi < 4; mi++) {
                const int r = wm + mi * 16 + g;
                const int kk = kf * 8 + tig;
                af[mi][0] = f2tf32(as[r       * AS_STRIDE + kk]);
                af[mi][1] = f2tf32(as[(r + 8) * AS_STRIDE + kk]);
                af[mi][2] = f2tf32(as[r       * AS_STRIDE + kk + 4]);
                af[mi][3] = f2tf32(as[(r + 8) * AS_STRIDE + kk + 4]);
            }
            uint32_t bf[4][2];
            #pragma unroll
            for (int ni = 0; ni < 4; ni++) {
                const int c = wn + ni * 8 + g;
                const int kk = kf * 8 + tig;
                if (TRANSB) {
                    bf[ni][0] = f2tf32(bs[c * BT_STRIDE + kk]);
                    bf[ni][1] = f2tf32(bs[c * BT_STRIDE + kk + 4]);
                } else {
                    bf[ni][0] = f2tf32(bs[(size_t)kk       * BS_STRIDE + c]);
                    bf[ni][1] = f2tf32(bs[(size_t)(kk + 4) * BS_STRIDE + c]);
                }
            }
            #pragma unroll
            for (int mi = 0; mi < 4; mi++)
                #pragma unroll
                for (int ni = 0; ni < 4; ni++) {
                    asm volatile(
                        "mma.sync.aligned.m16n8k8.row.col.f32.tf32.tf32.f32 "
                        "{%0,%1,%2,%3},{%4,%5,%6,%7},{%8,%9},{%0,%1,%2,%3};"
                        : "+f"(acc[mi][ni][0]), "+f"(acc[mi][ni][1]),
                          "+f"(acc[mi][ni][2]), "+f"(acc[mi][ni][3])
                        : "r"(af[mi][0]), "r"(af[mi][1]), "r"(af[mi][2]), "r"(af[mi][3]),
                          "r"(bf[ni][0]), "r"(bf[ni][1]));
                }
        }
        __syncthreads();
    }

    // Epilogue
    #pragma unroll
    for (int mi = 0; mi < 4; mi++) {
        const int r = row0 + wm + mi * 16 + g;
        #pragma unroll
        for (int ni = 0; ni < 4; ni++) {
            const int c = col0 + wn + ni * 8 + tig * 2;
            float2 v0 = make_float2(alpha * acc[mi][ni][0], alpha * acc[mi][ni][1]);
            float2 v1 = make_float2(alpha * acc[mi][ni][2], alpha * acc[mi][ni][3]);
            if (BIAS) {
                const float b0 = bias[c], b1 = bias[c + 1];
                v0.x += b0; v0.y += b1; v1.x += b0; v1.y += b1;
            }
            *reinterpret_cast<float2*>(&C[(size_t)r * ldc + c])       = v0;
            *reinterpret_cast<float2*>(&C[(size_t)(r + 8) * ldc + c]) = v1;
        }
    }
}

// ---------------------------------------------------------------------------
// Row softmax over rows of length TT. One block (256 thr) per row.
// ---------------------------------------------------------------------------
__global__ __launch_bounds__(256)
void softmax_kernel(float* __restrict__ att)
{
    float* row = att + (size_t)blockIdx.x * TT;
    const int tid = threadIdx.x;
    float v[8];
    float mx = -1e30f;
    #pragma unroll
    for (int i = 0; i < 8; i++) {
        v[i] = row[tid + (i << 8)];
        mx = fmaxf(mx, v[i]);
    }
    __shared__ float red[32];
    #pragma unroll
    for (int o = 16; o > 0; o >>= 1)
        mx = fmaxf(mx, __shfl_xor_sync(0xffffffffu, mx, o));
    if ((tid & 31) == 0) red[tid >> 5] = mx;
    __syncthreads();
    if (tid < 32) {
        float m2 = (tid < 8) ? red[tid] : -1e30f;
        #pragma unroll
        for (int o = 4; o > 0; o >>= 1)
            m2 = fmaxf(m2, __shfl_xor_sync(0xffffffffu, m2, o));
        if (tid == 0) red[0] = m2;
    }
    __syncthreads();
    mx = red[0];
    __syncthreads();

    float s = 0.f;
    #pragma unroll
    for (int i = 0; i < 8; i++) {
        v[i] = __expf(v[i] - mx);
        s += v[i];
    }
    #pragma unroll
    for (int o = 16; o > 0; o >>= 1)
        s += __shfl_xor_sync(0xffffffffu, s, o);
    if ((tid & 31) == 0) red[tid >> 5] = s;
    __syncthreads();
    if (tid < 32) {
        float s2 = (tid < 8) ? red[tid] : 0.f;
        #pragma unroll
        for (int o = 4; o > 0; o >>= 1)
            s2 += __shfl_xor_sync(0xffffffffu, s2, o);
        if (tid == 0) red[0] = s2;
    }
    __syncthreads();
    const float inv = 1.f / red[0];
    #pragma unroll
    for (int i = 0; i < 8; i++)
        row[tid + (i << 8)] = v[i] * inv;
}

// ---------------------------------------------------------------------------
extern "C" void kernel_launch(void* const* d_in, const int* in_sizes, int n_in,
                              void* d_out, int out_size)
{
    const float* x  = (const float*)d_in[0];   // [4,2048,768]
    const float* Wq = (const float*)d_in[1];   // [768,6144]
    const float* Wk = (const float*)d_in[2];
    const float* Wv = (const float*)d_in[3];
    const float* Wu = (const float*)d_in[4];   // [6144,768]
    const float* bu = (const float*)d_in[5];   // [768]
    float* out = (float*)d_out;                // [8192,768]

    float *q, *k, *v, *att, *ho;
    cudaGetSymbolAddress((void**)&q,   g_q);
    cudaGetSymbolAddress((void**)&k,   g_k);
    cudaGetSymbolAddress((void**)&v,   g_v);
    cudaGetSymbolAddress((void**)&att, g_att);
    cudaGetSymbolAddress((void**)&ho,  g_ho);

    const int SMEM = (2 * AS_BUF + 2 * (BN * BT_STRIDE)) * 4;  // 73728 B (max of variants)
    cudaFuncSetAttribute(tgemm<false, false>, cudaFuncAttributeMaxDynamicSharedMemorySize, SMEM);
    cudaFuncSetAttribute(tgemm<true,  false>, cudaFuncAttributeMaxDynamicSharedMemorySize, SMEM);
    cudaFuncSetAttribute(tgemm<false, true >, cudaFuncAttributeMaxDynamicSharedMemorySize, SMEM);

    const dim3 blk(256);
    const float alpha_scores = 1.0f / sqrtf((float)EE);

    // 1) QKV projections: [8192,768]@[768,6144]
    {
        dim3 g(HE / BN, MR / BM, 1);
        tgemm<false, false><<<g, blk, SMEM>>>(x, Wq, nullptr, q,
            MR, HE, EE, EE, HE, HE, 1, 0, 0, 0, 0, 0, 0, 1.f);
        tgemm<false, false><<<g, blk, SMEM>>>(x, Wk, nullptr, k,
            MR, HE, EE, EE, HE, HE, 1, 0, 0, 0, 0, 0, 0, 1.f);
        tgemm<false, false><<<g, blk, SMEM>>>(x, Wv, nullptr, v,
            MR, HE, EE, EE, HE, HE, 1, 0, 0, 0, 0, 0, 0, 1.f);
    }

    // 2) scores: per (b,h)  S = alpha * q_bh @ k_bh^T   [2048x2048]
    {
        dim3 g(TT / BN, TT / BM, BB * HH);
        tgemm<true, false><<<g, blk, SMEM>>>(q, k, nullptr, att,
            TT, TT, EE, HE, HE, TT,
            HH,
            (long)TT * HE, (long)EE,
            (long)TT * HE, (long)EE,
            (long)HH * TT * TT, (long)TT * TT,
            alpha_scores);
    }

    // 3) softmax over rows
    softmax_kernel<<<BB * HH * TT, blk>>>(att);

    // 4) O = att @ v_bh   [2048x2048]@[2048x768] -> ho (layout b,t,h,e)
    {
        dim3 g(EE / BN, TT / BM, BB * HH);
        tgemm<false, false><<<g, blk, SMEM>>>(att, v, nullptr, ho,
            TT, EE, TT, TT, HE, HE,
            HH,
            (long)HH * TT * TT, (long)TT * TT,
            (long)TT * HE, (long)EE,
            (long)TT * HE, (long)EE,
            1.f);
    }

    // 5) output projection + bias: [8192,6144]@[6144,768] + bu
    {
        dim3 g(EE / BN, MR / BM, 1);
        tgemm<false, true><<<g, blk, SMEM>>>(ho, Wu, bu, out,
            MR, EE, HE, HE, EE, EE, 1, 0, 0, 0, 0, 0, 0, 1.f);
    }
}

// round 4
// speedup vs baseline: 3.5819x; 1.1519x over previous
#include <cuda_runtime.h>
#include <math.h>
#include <stdint.h>

// Problem shape (fixed by the reference)
#define BB 4
#define TT 2048
#define EE 768
#define HH 8
#define HE 6144          // H*E
#define MR 8192          // B*T

// Scratch (allocation-free rule -> __device__ globals)
__device__ float g_q[(size_t)MR * HE];
__device__ float g_k[(size_t)MR * HE];
__device__ float g_v[(size_t)MR * HE];
__device__ float g_att[(size_t)BB * HH * (size_t)TT * TT];
__device__ float g_ho[(size_t)MR * HE];

// Tiling
#define BM 128
#define BN 128
#define BK 32
#define AS_STRIDE 36      // BK + 4  (bank-conflict-free fragment reads)
#define BS_STRIDE 136     // BN + 8
#define BT_STRIDE 36      // BK + 4
#define AS_BUF (BM * AS_STRIDE)            // 4608 floats per buffer

__device__ __forceinline__ uint32_t f2tf32(float f) {
    uint32_t u;
    asm("cvt.rna.tf32.f32 %0, %1;" : "=r"(u) : "f"(f));
    return u;
}
__device__ __forceinline__ void cp_async16(void* smem_dst, const void* gmem_src) {
    uint32_t s = (uint32_t)__cvta_generic_to_shared(smem_dst);
    asm volatile("cp.async.cg.shared.global [%0], [%1], 16;" :: "r"(s), "l"(gmem_src));
}
__device__ __forceinline__ void cp_commit() { asm volatile("cp.async.commit_group;" ::: "memory"); }
template<int N>
__device__ __forceinline__ void cp_wait() { asm volatile("cp.async.wait_group %0;" :: "n"(N) : "memory"); }

// ---------------------------------------------------------------------------
// tf32 tensor-core GEMM: C = alpha * A @ B(^T) (+ bias), row-major, batched
// via (batch, head) strides. All dims divisible by tile sizes (true here).
// __launch_bounds__(256, 2): 2 CTAs/SM -> 16 warps resident (occupancy fix).
// ---------------------------------------------------------------------------
template<bool TRANSB, bool BIAS>
__global__ __launch_bounds__(256, 2)
void tgemm(const float* __restrict__ A, const float* __restrict__ B,
           const float* __restrict__ bias, float* __restrict__ C,
           int M, int N, int K, int lda, int ldb, int ldc,
           int nh, long sAb, long sAh, long sBb, long sBh,
           long sCb, long sCh, float alpha)
{
    extern __shared__ float smem[];
    float* As = smem;                                  // 2 buffers
    float* Bs = smem + 2 * AS_BUF;
    const int BSZ = TRANSB ? (BN * BT_STRIDE) : (BK * BS_STRIDE);

    const int bz = blockIdx.z;
    const int bb = bz / nh;
    const int hh = bz - bb * nh;
    A += (long)bb * sAb + (long)hh * sAh;
    B += (long)bb * sBb + (long)hh * sBh;
    C += (long)bb * sCb + (long)hh * sCh;

    const int tid  = threadIdx.x;
    const int warp = tid >> 5, lane = tid & 31;
    const int g    = lane >> 2, tig = lane & 3;
    const int wm   = (warp >> 2) * 64;   // 2 warps along M
    const int wn   = (warp & 3)  * 32;   // 4 warps along N
    const int row0 = blockIdx.y * BM;
    const int col0 = blockIdx.x * BN;

    float acc[4][4][4] = {};  // [mi][ni][reg]

    // Loader index decompositions (all in-bounds; dims divide tiles exactly)
    const int a_m  = tid >> 3, a_k4 = (tid & 7) << 2;       // A: 4 passes, m += 32
    const int bn_k = tid >> 5, bn_n4 = (tid & 31) << 2;     // B normal: 4 passes, k += 8
    const int bt_n = tid >> 3, bt_k4 = (tid & 7) << 2;      // B trans:  4 passes, n += 32

    #define LOAD_TILE(K0, BUF)                                                        \
    {                                                                                 \
        float* as_ = As + (BUF) * AS_BUF;                                             \
        _Pragma("unroll")                                                             \
        for (int p = 0; p < 4; p++) {                                                 \
            int m = a_m + p * 32;                                                     \
            cp_async16(&as_[m * AS_STRIDE + a_k4],                                    \
                       &A[(size_t)(row0 + m) * lda + (K0) + a_k4]);                   \
        }                                                                             \
        float* bs_ = Bs + (BUF) * BSZ;                                                \
        if (TRANSB) {                                                                 \
            _Pragma("unroll")                                                         \
            for (int p = 0; p < 4; p++) {                                             \
                int n = bt_n + p * 32;                                                \
                cp_async16(&bs_[n * BT_STRIDE + bt_k4],                               \
                           &B[(size_t)(col0 + n) * ldb + (K0) + bt_k4]);              \
            }                                                                         \
        } else {                                                                      \
            _Pragma("unroll")                                                         \
            for (int p = 0; p < 4; p++) {                                             \
                int kk = bn_k + p * 8;                                                \
                cp_async16(&bs_[kk * BS_STRIDE + bn_n4],                              \
                           &B[(size_t)((K0) + kk) * ldb + col0 + bn_n4]);             \
            }                                                                         \
        }                                                                             \
        cp_commit();                                                                  \
    }

    LOAD_TILE(0, 0);
    const int ntiles = K / BK;

    for (int kt = 0; kt < ntiles; kt++) {
        const int buf = kt & 1;
        if (kt + 1 < ntiles) {
            LOAD_TILE((kt + 1) * BK, buf ^ 1);
            cp_wait<1>();
        } else {
            cp_wait<0>();
        }
        __syncthreads();

        const float* as = As + buf * AS_BUF;
        const float* bs = Bs + buf * BSZ;

        #pragma unroll
        for (int kf = 0; kf < 4; kf++) {
            uint32_t af[4][4];
            #pragma unroll
            for (int mi = 0; mi < 4; mi++) {
                const int r = wm + mi * 16 + g;
                const int kk = kf * 8 + tig;
                af[mi][0] = f2tf32(as[r       * AS_STRIDE + kk]);
                af[mi][1] = f2tf32(as[(r + 8) * AS_STRIDE + kk]);
                af[mi][2] = f2tf32(as[r       * AS_STRIDE + kk + 4]);
                af[mi][3] = f2tf32(as[(r + 8) * AS_STRIDE + kk + 4]);
            }
            uint32_t bf[4][2];
            #pragma unroll
            for (int ni = 0; ni < 4; ni++) {
                const int c = wn + ni * 8 + g;
                const int kk = kf * 8 + tig;
                if (TRANSB) {
                    bf[ni][0] = f2tf32(bs[c * BT_STRIDE + kk]);
                    bf[ni][1] = f2tf32(bs[c * BT_STRIDE + kk + 4]);
                } else {
                    bf[ni][0] = f2tf32(bs[(size_t)kk       * BS_STRIDE + c]);
                    bf[ni][1] = f2tf32(bs[(size_t)(kk + 4) * BS_STRIDE + c]);
                }
            }
            #pragma unroll
            for (int mi = 0; mi < 4; mi++)
                #pragma unroll
                for (int ni = 0; ni < 4; ni++) {
                    asm volatile(
                        "mma.sync.aligned.m16n8k8.row.col.f32.tf32.tf32.f32 "
                        "{%0,%1,%2,%3},{%4,%5,%6,%7},{%8,%9},{%0,%1,%2,%3};"
                        : "+f"(acc[mi][ni][0]), "+f"(acc[mi][ni][1]),
                          "+f"(acc[mi][ni][2]), "+f"(acc[mi][ni][3])
                        : "r"(af[mi][0]), "r"(af[mi][1]), "r"(af[mi][2]), "r"(af[mi][3]),
                          "r"(bf[ni][0]), "r"(bf[ni][1]));
                }
        }
        __syncthreads();
    }

    // Epilogue
    #pragma unroll
    for (int mi = 0; mi < 4; mi++) {
        const int r = row0 + wm + mi * 16 + g;
        #pragma unroll
        for (int ni = 0; ni < 4; ni++) {
            const int c = col0 + wn + ni * 8 + tig * 2;
            float2 v0 = make_float2(alpha * acc[mi][ni][0], alpha * acc[mi][ni][1]);
            float2 v1 = make_float2(alpha * acc[mi][ni][2], alpha * acc[mi][ni][3]);
            if (BIAS) {
                const float b0 = bias[c], b1 = bias[c + 1];
                v0.x += b0; v0.y += b1; v1.x += b0; v1.y += b1;
            }
            *reinterpret_cast<float2*>(&C[(size_t)r * ldc + c])       = v0;
            *reinterpret_cast<float2*>(&C[(size_t)(r + 8) * ldc + c]) = v1;
        }
    }
}

// ---------------------------------------------------------------------------
// Row softmax over rows of length TT. One block (256 thr) per row.
// ---------------------------------------------------------------------------
__global__ __launch_bounds__(256, 2)
void softmax_kernel(float* __restrict__ att)
{
    float* row = att + (size_t)blockIdx.x * TT;
    const int tid = threadIdx.x;
    float v[8];
    float mx = -1e30f;
    #pragma unroll
    for (int i = 0; i < 8; i++) {
        v[i] = row[tid + (i << 8)];
        mx = fmaxf(mx, v[i]);
    }
    __shared__ float red[32];
    #pragma unroll
    for (int o = 16; o > 0; o >>= 1)
        mx = fmaxf(mx, __shfl_xor_sync(0xffffffffu, mx, o));
    if ((tid & 31) == 0) red[tid >> 5] = mx;
    __syncthreads();
    if (tid < 32) {
        float m2 = (tid < 8) ? red[tid] : -1e30f;
        #pragma unroll
        for (int o = 4; o > 0; o >>= 1)
            m2 = fmaxf(m2, __shfl_xor_sync(0xffffffffu, m2, o));
        if (tid == 0) red[0] = m2;
    }
    __syncthreads();
    mx = red[0];
    __syncthreads();

    float s = 0.f;
    #pragma unroll
    for (int i = 0; i < 8; i++) {
        v[i] = __expf(v[i] - mx);
        s += v[i];
    }
    #pragma unroll
    for (int o = 16; o > 0; o >>= 1)
        s += __shfl_xor_sync(0xffffffffu, s, o);
    if ((tid & 31) == 0) red[tid >> 5] = s;
    __syncthreads();
    if (tid < 32) {
        float s2 = (tid < 8) ? red[tid] : 0.f;
        #pragma unroll
        for (int o = 4; o > 0; o >>= 1)
            s2 += __shfl_xor_sync(0xffffffffu, s2, o);
        if (tid == 0) red[0] = s2;
    }
    __syncthreads();
    const float inv = 1.f / red[0];
    #pragma unroll
    for (int i = 0; i < 8; i++)
        row[tid + (i << 8)] = v[i] * inv;
}

// ---------------------------------------------------------------------------
extern "C" void kernel_launch(void* const* d_in, const int* in_sizes, int n_in,
                              void* d_out, int out_size)
{
    const float* x  = (const float*)d_in[0];   // [4,2048,768]
    const float* Wq = (const float*)d_in[1];   // [768,6144]
    const float* Wk = (const float*)d_in[2];
    const float* Wv = (const float*)d_in[3];
    const float* Wu = (const float*)d_in[4];   // [6144,768]
    const float* bu = (const float*)d_in[5];   // [768]
    float* out = (float*)d_out;                // [8192,768]

    float *q, *k, *v, *att, *ho;
    cudaGetSymbolAddress((void**)&q,   g_q);
    cudaGetSymbolAddress((void**)&k,   g_k);
    cudaGetSymbolAddress((void**)&v,   g_v);
    cudaGetSymbolAddress((void**)&att, g_att);
    cudaGetSymbolAddress((void**)&ho,  g_ho);

    const int SMEM = (2 * AS_BUF + 2 * (BN * BT_STRIDE)) * 4;  // 73728 B (max of variants)
    cudaFuncSetAttribute(tgemm<false, false>, cudaFuncAttributeMaxDynamicSharedMemorySize, SMEM);
    cudaFuncSetAttribute(tgemm<true,  false>, cudaFuncAttributeMaxDynamicSharedMemorySize, SMEM);
    cudaFuncSetAttribute(tgemm<false, true >, cudaFuncAttributeMaxDynamicSharedMemorySize, SMEM);

    const dim3 blk(256);
    const float alpha_scores = 1.0f / sqrtf((float)EE);

    // 1) QKV projections: [8192,768]@[768,6144]
    {
        dim3 g(HE / BN, MR / BM, 1);
        tgemm<false, false><<<g, blk, SMEM>>>(x, Wq, nullptr, q,
            MR, HE, EE, EE, HE, HE, 1, 0, 0, 0, 0, 0, 0, 1.f);
        tgemm<false, false><<<g, blk, SMEM>>>(x, Wk, nullptr, k,
            MR, HE, EE, EE, HE, HE, 1, 0, 0, 0, 0, 0, 0, 1.f);
        tgemm<false, false><<<g, blk, SMEM>>>(x, Wv, nullptr, v,
            MR, HE, EE, EE, HE, HE, 1, 0, 0, 0, 0, 0, 0, 1.f);
    }

    // 2) scores: per (b,h)  S = alpha * q_bh @ k_bh^T   [2048x2048]
    {
        dim3 g(TT / BN, TT / BM, BB * HH);
        tgemm<true, false><<<g, blk, SMEM>>>(q, k, nullptr, att,
            TT, TT, EE, HE, HE, TT,
            HH,
            (long)TT * HE, (long)EE,
            (long)TT * HE, (long)EE,
            (long)HH * TT * TT, (long)TT * TT,
            alpha_scores);
    }

    // 3) softmax over rows
    softmax_kernel<<<BB * HH * TT, blk>>>(att);

    // 4) O = att @ v_bh   [2048x2048]@[2048x768] -> ho (layout b,t,h,e)
    {
        dim3 g(EE / BN, TT / BM, BB * HH);
        tgemm<false, false><<<g, blk, SMEM>>>(att, v, nullptr, ho,
            TT, EE, TT, TT, HE, HE,
            HH,
            (long)HH * TT * TT, (long)TT * TT,
            (long)TT * HE, (long)EE,
            (long)TT * HE, (long)EE,
            1.f);
    }

    // 5) output projection + bias: [8192,6144]@[6144,768] + bu
    {
        dim3 g(EE / BN, MR / BM, 1);
        tgemm<false, true><<<g, blk, SMEM>>>(ho, Wu, bu, out,
            MR, EE, HE, HE, EE, EE, 1, 0, 0, 0, 0, 0, 0, 1.f);
    }
}

// round 5
// speedup vs baseline: 4.0657x; 1.1351x over previous
#include <cuda_runtime.h>
#include <math.h>
#include <stdint.h>

// Problem shape (fixed by the reference)
#define BB 4
#define TT 2048
#define EE 768
#define HH 8
#define HE 6144          // H*E
#define MR 8192          // B*T

// Scratch (allocation-free rule -> __device__ globals)
__device__ float g_x[(size_t)MR * EE];                  // x rounded to tf32
__device__ float g_qkv[(size_t)3 * MR * HE];            // q | k | v
__device__ float g_wt[(size_t)4 * HE * EE];             // WqT | WkT | WvT | WuT (tf32)
__device__ float g_att[(size_t)BB * HH * (size_t)TT * TT];
__device__ float g_vt[(size_t)MR * HE];                 // v^T per (b,h): [b,h,e,t] (tf32)
__device__ float g_ho[(size_t)MR * HE];

// Tiling
#define BM 128
#define BN 128
#define BK 32
#define TS 36                       // padded stride (floats), conflict-free LDSM
#define TILE_FLOATS (128 * TS)      // 4608
#define TILE_BYTES (TILE_FLOATS * 4)  // 18432
#define SMEM_TOTAL (4 * TILE_BYTES)   // A0,A1,B0,B1 = 73728 B

__device__ __forceinline__ uint32_t f2tf32(float f) {
    uint32_t u;
    asm("cvt.rna.tf32.f32 %0, %1;" : "=r"(u) : "f"(f));
    return u;
}
__device__ __forceinline__ float roundtf32(float f) {
    return __uint_as_float(f2tf32(f));
}
__device__ __forceinline__ void cp_async16(void* smem_dst, const void* gmem_src) {
    uint32_t s = (uint32_t)__cvta_generic_to_shared(smem_dst);
    asm volatile("cp.async.cg.shared.global [%0], [%1], 16;" :: "r"(s), "l"(gmem_src));
}
__device__ __forceinline__ void cp_commit() { asm volatile("cp.async.commit_group;" ::: "memory"); }
template<int N>
__device__ __forceinline__ void cp_wait() { asm volatile("cp.async.wait_group %0;" :: "n"(N) : "memory"); }
__device__ __forceinline__ void ldsm_x4(uint32_t (&d)[4], uint32_t addr) {
    asm volatile("ldmatrix.sync.aligned.m8n8.x4.shared.b16 {%0,%1,%2,%3}, [%4];"
        : "=r"(d[0]), "=r"(d[1]), "=r"(d[2]), "=r"(d[3]) : "r"(addr));
}

// ---------------------------------------------------------------------------
// tf32 tensor-core GEMM via ldmatrix. C = alpha * A[M,K] @ B[N,K]^T (+bias).
// A, B K-major in gmem, data pre-rounded to tf32. Batched (b,h) strides.
// ---------------------------------------------------------------------------
template<bool BIAS, bool ROUND>
__global__ __launch_bounds__(256, 2)
void tgemm(const float* __restrict__ A, const float* __restrict__ B,
           const float* __restrict__ bias, float* __restrict__ C,
           int K, int lda, int ldb, int ldc,
           int nh, long sAb, long sAh, long sBb, long sBh,
           long sCb, long sCh, float alpha)
{
    extern __shared__ float smem[];
    const uint32_t smem_u = (uint32_t)__cvta_generic_to_shared(smem);

    const int bz = blockIdx.z;
    const int bb = bz / nh;
    const int hh = bz - bb * nh;
    A += (long)bb * sAb + (long)hh * sAh;
    B += (long)bb * sBb + (long)hh * sBh;
    C += (long)bb * sCb + (long)hh * sCh;

    const int tid  = threadIdx.x;
    const int warp = tid >> 5, lane = tid & 31;
    const int g    = lane >> 2, tig = lane & 3;
    const int r8   = lane & 7, j = lane >> 3;      // LDSM lane roles
    const int wm   = (warp >> 2) * 64;   // 2 warps along M
    const int wn   = (warp & 3)  * 32;   // 4 warps along N
    const int row0 = blockIdx.y * BM;
    const int col0 = blockIdx.x * BN;

    // LDSM byte offsets within a tile buffer (add kf*32 bytes per k-fragment)
    uint32_t aoff[4], boff[2];
    #pragma unroll
    for (int mi = 0; mi < 4; mi++)
        aoff[mi] = ((wm + mi * 16 + (j & 1) * 8 + r8) * TS + (j >> 1) * 4) * 4;
    #pragma unroll
    for (int p = 0; p < 2; p++)
        boff[p] = ((wn + p * 16 + (j >> 1) * 8 + r8) * TS + (j & 1) * 4) * 4;

    float acc[4][4][4] = {};  // [mi][ni][reg]

    // Loader: tiles are 128 rows x 32 floats (8 x 16B chunks per row)
    const int l_r = tid >> 3, l_kc = (tid & 7) << 2;

    #define LOAD_TILE(K0, BUF)                                                        \
    {                                                                                 \
        float* as_ = smem + (BUF) * TILE_FLOATS;                                      \
        float* bs_ = smem + (2 + (BUF)) * TILE_FLOATS;                                \
        _Pragma("unroll")                                                             \
        for (int p = 0; p < 4; p++) {                                                 \
            int rr = l_r + p * 32;                                                    \
            cp_async16(&as_[rr * TS + l_kc],                                          \
                       &A[(size_t)(row0 + rr) * lda + (K0) + l_kc]);                  \
        }                                                                             \
        _Pragma("unroll")                                                             \
        for (int p = 0; p < 4; p++) {                                                 \
            int rr = l_r + p * 32;                                                    \
            cp_async16(&bs_[rr * TS + l_kc],                                          \
                       &B[(size_t)(col0 + rr) * ldb + (K0) + l_kc]);                  \
        }                                                                             \
        cp_commit();                                                                  \
    }

    LOAD_TILE(0, 0);
    const int ntiles = K / BK;

    for (int kt = 0; kt < ntiles; kt++) {
        const int buf = kt & 1;
        if (kt + 1 < ntiles) {
            LOAD_TILE((kt + 1) * BK, buf ^ 1);
            cp_wait<1>();
        } else {
            cp_wait<0>();
        }
        __syncthreads();

        const uint32_t as_u = smem_u + buf * TILE_BYTES;
        const uint32_t bs_u = smem_u + (2 + buf) * TILE_BYTES;

        #pragma unroll
        for (int kf = 0; kf < 4; kf++) {
            uint32_t af[4][4];
            #pragma unroll
            for (int mi = 0; mi < 4; mi++)
                ldsm_x4(af[mi], as_u + aoff[mi] + kf * 32);
            uint32_t bf[2][4];
            #pragma unroll
            for (int p = 0; p < 2; p++)
                ldsm_x4(bf[p], bs_u + boff[p] + kf * 32);

            #pragma unroll
            for (int mi = 0; mi < 4; mi++)
                #pragma unroll
                for (int ni = 0; ni < 4; ni++) {
                    const uint32_t b0 = bf[ni >> 1][(ni & 1) * 2 + 0];
                    const uint32_t b1 = bf[ni >> 1][(ni & 1) * 2 + 1];
                    asm volatile(
                        "mma.sync.aligned.m16n8k8.row.col.f32.tf32.tf32.f32 "
                        "{%0,%1,%2,%3},{%4,%5,%6,%7},{%8,%9},{%0,%1,%2,%3};"
                        : "+f"(acc[mi][ni][0]), "+f"(acc[mi][ni][1]),
                          "+f"(acc[mi][ni][2]), "+f"(acc[mi][ni][3])
                        : "r"(af[mi][0]), "r"(af[mi][1]), "r"(af[mi][2]), "r"(af[mi][3]),
                          "r"(b0), "r"(b1));
                }
        }
        __syncthreads();
    }

    // Epilogue
    #pragma unroll
    for (int mi = 0; mi < 4; mi++) {
        const int r = row0 + wm + mi * 16 + g;
        #pragma unroll
        for (int ni = 0; ni < 4; ni++) {
            const int c = col0 + wn + ni * 8 + tig * 2;
            float2 v0 = make_float2(alpha * acc[mi][ni][0], alpha * acc[mi][ni][1]);
            float2 v1 = make_float2(alpha * acc[mi][ni][2], alpha * acc[mi][ni][3]);
            if (BIAS) {
                const float b0 = bias[c], b1 = bias[c + 1];
                v0.x += b0; v0.y += b1; v1.x += b0; v1.y += b1;
            }
            if (ROUND) {
                v0.x = roundtf32(v0.x); v0.y = roundtf32(v0.y);
                v1.x = roundtf32(v1.x); v1.y = roundtf32(v1.y);
            }
            *reinterpret_cast<float2*>(&C[(size_t)r * ldc + c])       = v0;
            *reinterpret_cast<float2*>(&C[(size_t)(r + 8) * ldc + c]) = v1;
        }
    }
    #undef LOAD_TILE
}

// ---------------------------------------------------------------------------
// Tiled transpose with tf32 rounding: dst[c, r] = tf32(src[r, c]), batched.
// ---------------------------------------------------------------------------
__global__ __launch_bounds__(256)
void transpose_kernel(const float* __restrict__ src, float* __restrict__ dst,
                      int lds, int ldd,
                      int nh, long sSb, long sSh, long sDb, long sDh)
{
    __shared__ float t[32][33];
    const int bz = blockIdx.z;
    const int bb = bz / nh;
    const int hh = bz - bb * nh;
    src += (long)bb * sSb + (long)hh * sSh;
    dst += (long)bb * sDb + (long)hh * sDh;

    const int bx = blockIdx.x * 32;   // C dim
    const int by = blockIdx.y * 32;   // R dim
    const int tx = threadIdx.x & 31;
    const int ty = threadIdx.x >> 5;  // 0..7

    #pragma unroll
    for (int jj = 0; jj < 4; jj++)
        t[ty + 8 * jj][tx] = roundtf32(src[(size_t)(by + ty + 8 * jj) * lds + bx + tx]);
    __syncthreads();
    #pragma unroll
    for (int jj = 0; jj < 4; jj++)
        dst[(size_t)(bx + ty + 8 * jj) * ldd + by + tx] = t[tx][ty + 8 * jj];
}

// Elementwise tf32 rounding pass (for x)
__global__ __launch_bounds__(256)
void round_kernel(const float* __restrict__ src, float* __restrict__ dst, int n4)
{
    int i = blockIdx.x * 256 + threadIdx.x;
    if (i < n4) {
        float4 v = reinterpret_cast<const float4*>(src)[i];
        v.x = roundtf32(v.x); v.y = roundtf32(v.y);
        v.z = roundtf32(v.z); v.w = roundtf32(v.w);
        reinterpret_cast<float4*>(dst)[i] = v;
    }
}

// ---------------------------------------------------------------------------
// Row softmax over rows of length TT; writes tf32-rounded probabilities.
// ---------------------------------------------------------------------------
__global__ __launch_bounds__(256, 2)
void softmax_kernel(float* __restrict__ att)
{
    float* row = att + (size_t)blockIdx.x * TT;
    const int tid = threadIdx.x;
    float v[8];
    float mx = -1e30f;
    #pragma unroll
    for (int i = 0; i < 8; i++) {
        v[i] = row[tid + (i << 8)];
        mx = fmaxf(mx, v[i]);
    }
    __shared__ float red[32];
    #pragma unroll
    for (int o = 16; o > 0; o >>= 1)
        mx = fmaxf(mx, __shfl_xor_sync(0xffffffffu, mx, o));
    if ((tid & 31) == 0) red[tid >> 5] = mx;
    __syncthreads();
    if (tid < 32) {
        float m2 = (tid < 8) ? red[tid] : -1e30f;
        #pragma unroll
        for (int o = 4; o > 0; o >>= 1)
            m2 = fmaxf(m2, __shfl_xor_sync(0xffffffffu, m2, o));
        if (tid == 0) red[0] = m2;
    }
    __syncthreads();
    mx = red[0];
    __syncthreads();

    float s = 0.f;
    #pragma unroll
    for (int i = 0; i < 8; i++) {
        v[i] = __expf(v[i] - mx);
        s += v[i];
    }
    #pragma unroll
    for (int o = 16; o > 0; o >>= 1)
        s += __shfl_xor_sync(0xffffffffu, s, o);
    if ((tid & 31) == 0) red[tid >> 5] = s;
    __syncthreads();
    if (tid < 32) {
        float s2 = (tid < 8) ? red[tid] : 0.f;
        #pragma unroll
        for (int o = 4; o > 0; o >>= 1)
            s2 += __shfl_xor_sync(0xffffffffu, s2, o);
        if (tid == 0) red[0] = s2;
    }
    __syncthreads();
    const float inv = 1.f / red[0];
    #pragma unroll
    for (int i = 0; i < 8; i++)
        row[tid + (i << 8)] = roundtf32(v[i] * inv);
}

// ---------------------------------------------------------------------------
extern "C" void kernel_launch(void* const* d_in, const int* in_sizes, int n_in,
                              void* d_out, int out_size)
{
    const float* x  = (const float*)d_in[0];   // [4,2048,768]
    const float* Wq = (const float*)d_in[1];   // [768,6144]
    const float* Wk = (const float*)d_in[2];
    const float* Wv = (const float*)d_in[3];
    const float* Wu = (const float*)d_in[4];   // [6144,768]
    const float* bu = (const float*)d_in[5];   // [768]
    float* out = (float*)d_out;                // [8192,768]

    float *gx, *qkv, *wt, *att, *vt, *ho;
    cudaGetSymbolAddress((void**)&gx,  g_x);
    cudaGetSymbolAddress((void**)&qkv, g_qkv);
    cudaGetSymbolAddress((void**)&wt,  g_wt);
    cudaGetSymbolAddress((void**)&att, g_att);
    cudaGetSymbolAddress((void**)&vt,  g_vt);
    cudaGetSymbolAddress((void**)&ho,  g_ho);

    float* q = qkv;
    float* k = qkv + (size_t)MR * HE;
    float* v = qkv + (size_t)2 * MR * HE;
    const long WSZ = (long)HE * EE;

    cudaFuncSetAttribute(tgemm<false, true>,  cudaFuncAttributeMaxDynamicSharedMemorySize, SMEM_TOTAL);
    cudaFuncSetAttribute(tgemm<true,  false>, cudaFuncAttributeMaxDynamicSharedMemorySize, SMEM_TOTAL);

    const dim3 blk(256);
    const float alpha_scores = 1.0f / sqrtf((float)EE);

    // 0) preprocessing: round x; transpose+round weights -> K-major [N,K]
    round_kernel<<<(MR * EE / 4 + 255) / 256, blk>>>(x, gx, MR * EE / 4);
    transpose_kernel<<<dim3(HE/32, EE/32, 1), blk>>>(Wq, wt + 0*WSZ, HE, EE, 1, 0,0,0,0);
    transpose_kernel<<<dim3(HE/32, EE/32, 1), blk>>>(Wk, wt + 1*WSZ, HE, EE, 1, 0,0,0,0);
    transpose_kernel<<<dim3(HE/32, EE/32, 1), blk>>>(Wv, wt + 2*WSZ, HE, EE, 1, 0,0,0,0);
    transpose_kernel<<<dim3(EE/32, HE/32, 1), blk>>>(Wu, wt + 3*WSZ, EE, HE, 1, 0,0,0,0);

    // 1) QKV projections (batched z=3): qkv[z] = x @ W[z]^T-layout -> [8192,6144]
    tgemm<false, true><<<dim3(HE/128, MR/128, 3), blk, SMEM_TOTAL>>>(
        gx, wt, nullptr, qkv,
        EE, EE, EE, HE,
        1, 0, 0, WSZ, 0, (long)MR * HE, 0, 1.f);

    // 2) transpose v -> vt [b,h,e,t]  (already tf32; rounding is idempotent)
    transpose_kernel<<<dim3(EE/32, TT/32, BB*HH), blk>>>(
        v, vt, HE, TT,
        HH, (long)TT * HE, (long)EE, (long)HH * EE * TT, (long)EE * TT);

    // 3) scores: att[b,h] = alpha * q_bh @ k_bh^T
    tgemm<false, true><<<dim3(TT/128, TT/128, BB*HH), blk, SMEM_TOTAL>>>(
        q, k, nullptr, att,
        EE, HE, HE, TT,
        HH, (long)TT * HE, (long)EE, (long)TT * HE, (long)EE,
        (long)HH * TT * TT, (long)TT * TT, alpha_scores);

    // 4) softmax (writes tf32-rounded)
    softmax_kernel<<<BB * HH * TT, blk>>>(att);

    // 5) O = att @ vt^T  -> ho [b,t,h,e]
    tgemm<false, true><<<dim3(EE/128, TT/128, BB*HH), blk, SMEM_TOTAL>>>(
        att, vt, nullptr, ho,
        TT, TT, TT, HE,
        HH, (long)HH * TT * TT, (long)TT * TT,
        (long)HH * EE * TT, (long)EE * TT,
        (long)TT * HE, (long)EE, 1.f);

    // 6) output projection + bias (B = WuT); final output NOT rounded
    tgemm<true, false><<<dim3(EE/128, MR/128, 1), blk, SMEM_TOTAL>>>(
        ho, wt + 3*WSZ, bu, out,
        HE, HE, HE, EE,
        1, 0, 0, 0, 0, 0, 0, 1.f);
}

// round 6
// speedup vs baseline: 4.2105x; 1.0356x over previous
#include <cuda_runtime.h>
#include <math.h>
#include <stdint.h>

// Problem shape (fixed by the reference)
#define BB 4
#define TT 2048
#define EE 768
#define HH 8
#define HE 6144          // H*E
#define MR 8192          // B*T

// Scratch (allocation-free rule -> __device__ globals)
__device__ float g_x[(size_t)MR * EE];                  // x rounded to tf32
__device__ float g_qkv[(size_t)3 * MR * HE];            // q | k | v
__device__ float g_wt[(size_t)4 * HE * EE];             // WqT | WkT | WvT | WuT (tf32)
__device__ float g_att[(size_t)BB * HH * (size_t)TT * TT];
__device__ float g_vt[(size_t)MR * HE];                 // v^T per (b,h): [b,h,e,t] (tf32)
__device__ float g_ho[(size_t)MR * HE];

// Tiling
#define BM 128
#define BN 128
#define BK 32
#define TS 36                       // padded stride (floats), conflict-free LDSM
#define TILE_FLOATS (128 * TS)      // 4608
#define TILE_BYTES (TILE_FLOATS * 4)  // 18432
#define SMEM_TOTAL (4 * TILE_BYTES)   // A0,A1,B0,B1 = 73728 B

__device__ __forceinline__ uint32_t f2tf32(float f) {
    uint32_t u;
    asm("cvt.rna.tf32.f32 %0, %1;" : "=r"(u) : "f"(f));
    return u;
}
__device__ __forceinline__ float roundtf32(float f) {
    return __uint_as_float(f2tf32(f));
}
__device__ __forceinline__ void cp_async16(void* smem_dst, const void* gmem_src) {
    uint32_t s = (uint32_t)__cvta_generic_to_shared(smem_dst);
    asm volatile("cp.async.cg.shared.global [%0], [%1], 16;" :: "r"(s), "l"(gmem_src));
}
__device__ __forceinline__ void cp_commit() { asm volatile("cp.async.commit_group;" ::: "memory"); }
template<int N>
__device__ __forceinline__ void cp_wait() { asm volatile("cp.async.wait_group %0;" :: "n"(N) : "memory"); }
__device__ __forceinline__ void ldsm_x4(uint32_t (&d)[4], uint32_t addr) {
    asm volatile("ldmatrix.sync.aligned.m8n8.x4.shared.b16 {%0,%1,%2,%3}, [%4];"
        : "=r"(d[0]), "=r"(d[1]), "=r"(d[2]), "=r"(d[3]) : "r"(addr));
}

// ---------------------------------------------------------------------------
// tf32 tensor-core GEMM via ldmatrix. C = alpha * A[M,K] @ B[N,K]^T (+bias).
// A, B K-major in gmem, data pre-rounded to tf32. Batched (b,h) strides.
// 4 warps (128 thr), warp tile 64x64 -> 8 LDSM : 128 HMMA per K-tile.
// ---------------------------------------------------------------------------
template<bool BIAS, bool ROUND>
__global__ __launch_bounds__(128, 2)
void tgemm(const float* __restrict__ A, const float* __restrict__ B,
           const float* __restrict__ bias, float* __restrict__ C,
           int K, int lda, int ldb, int ldc,
           int nh, long sAb, long sAh, long sBb, long sBh,
           long sCb, long sCh, float alpha)
{
    extern __shared__ float smem[];
    const uint32_t smem_u = (uint32_t)__cvta_generic_to_shared(smem);

    const int bz = blockIdx.z;
    const int bb = bz / nh;
    const int hh = bz - bb * nh;
    A += (long)bb * sAb + (long)hh * sAh;
    B += (long)bb * sBb + (long)hh * sBh;
    C += (long)bb * sCb + (long)hh * sCh;

    const int tid  = threadIdx.x;
    const int warp = tid >> 5, lane = tid & 31;
    const int g    = lane >> 2, tig = lane & 3;
    const int r8   = lane & 7, j = lane >> 3;      // LDSM lane roles
    const int wm   = (warp >> 1) * 64;   // 2 warps along M
    const int wn   = (warp & 1)  * 64;   // 2 warps along N
    const int row0 = blockIdx.y * BM;
    const int col0 = blockIdx.x * BN;

    // LDSM byte offsets within a tile buffer (add kf*32 bytes per k-fragment)
    uint32_t aoff[4], boff[4];
    #pragma unroll
    for (int mi = 0; mi < 4; mi++)
        aoff[mi] = ((wm + mi * 16 + (j & 1) * 8 + r8) * TS + (j >> 1) * 4) * 4;
    #pragma unroll
    for (int p = 0; p < 4; p++)
        boff[p] = ((wn + p * 16 + (j >> 1) * 8 + r8) * TS + (j & 1) * 4) * 4;

    float acc[4][8][4] = {};  // [mi][ni][reg]

    // Loader: tiles are 128 rows x 32 floats (8 x 16B chunks per row).
    // 128 threads: 8 passes per operand.
    #define LOAD_TILE(K0, BUF)                                                        \
    {                                                                                 \
        float* as_ = smem + (BUF) * TILE_FLOATS;                                      \
        float* bs_ = smem + (2 + (BUF)) * TILE_FLOATS;                                \
        _Pragma("unroll")                                                             \
        for (int p = 0; p < 8; p++) {                                                 \
            int id = p * 128 + tid;                                                   \
            int rr = id >> 3, kc = (id & 7) << 2;                                     \
            cp_async16(&as_[rr * TS + kc],                                            \
                       &A[(size_t)(row0 + rr) * lda + (K0) + kc]);                    \
        }                                                                             \
        _Pragma("unroll")                                                             \
        for (int p = 0; p < 8; p++) {                                                 \
            int id = p * 128 + tid;                                                   \
            int rr = id >> 3, kc = (id & 7) << 2;                                     \
            cp_async16(&bs_[rr * TS + kc],                                            \
                       &B[(size_t)(col0 + rr) * ldb + (K0) + kc]);                    \
        }                                                                             \
        cp_commit();                                                                  \
    }

    LOAD_TILE(0, 0);
    const int ntiles = K / BK;

    for (int kt = 0; kt < ntiles; kt++) {
        const int buf = kt & 1;
        if (kt + 1 < ntiles) {
            LOAD_TILE((kt + 1) * BK, buf ^ 1);
            cp_wait<1>();
        } else {
            cp_wait<0>();
        }
        __syncthreads();

        const uint32_t as_u = smem_u + buf * TILE_BYTES;
        const uint32_t bs_u = smem_u + (2 + buf) * TILE_BYTES;

        #pragma unroll
        for (int kf = 0; kf < 4; kf++) {
            uint32_t af[4][4];
            #pragma unroll
            for (int mi = 0; mi < 4; mi++)
                ldsm_x4(af[mi], as_u + aoff[mi] + kf * 32);
            uint32_t bf[4][4];
            #pragma unroll
            for (int p = 0; p < 4; p++)
                ldsm_x4(bf[p], bs_u + boff[p] + kf * 32);

            #pragma unroll
            for (int mi = 0; mi < 4; mi++)
                #pragma unroll
                for (int ni = 0; ni < 8; ni++) {
                    const uint32_t b0 = bf[ni >> 1][(ni & 1) * 2 + 0];
                    const uint32_t b1 = bf[ni >> 1][(ni & 1) * 2 + 1];
                    asm volatile(
                        "mma.sync.aligned.m16n8k8.row.col.f32.tf32.tf32.f32 "
                        "{%0,%1,%2,%3},{%4,%5,%6,%7},{%8,%9},{%0,%1,%2,%3};"
                        : "+f"(acc[mi][ni][0]), "+f"(acc[mi][ni][1]),
                          "+f"(acc[mi][ni][2]), "+f"(acc[mi][ni][3])
                        : "r"(af[mi][0]), "r"(af[mi][1]), "r"(af[mi][2]), "r"(af[mi][3]),
                          "r"(b0), "r"(b1));
                }
        }
        __syncthreads();
    }

    // Epilogue
    #pragma unroll
    for (int mi = 0; mi < 4; mi++) {
        const int r = row0 + wm + mi * 16 + g;
        #pragma unroll
        for (int ni = 0; ni < 8; ni++) {
            const int c = col0 + wn + ni * 8 + tig * 2;
            float2 v0 = make_float2(alpha * acc[mi][ni][0], alpha * acc[mi][ni][1]);
            float2 v1 = make_float2(alpha * acc[mi][ni][2], alpha * acc[mi][ni][3]);
            if (BIAS) {
                const float b0 = bias[c], b1 = bias[c + 1];
                v0.x += b0; v0.y += b1; v1.x += b0; v1.y += b1;
            }
            if (ROUND) {
                v0.x = roundtf32(v0.x); v0.y = roundtf32(v0.y);
                v1.x = roundtf32(v1.x); v1.y = roundtf32(v1.y);
            }
            *reinterpret_cast<float2*>(&C[(size_t)r * ldc + c])       = v0;
            *reinterpret_cast<float2*>(&C[(size_t)(r + 8) * ldc + c]) = v1;
        }
    }
    #undef LOAD_TILE
}

// ---------------------------------------------------------------------------
// Tiled transpose with tf32 rounding: dst[c, r] = tf32(src[r, c]), batched.
// ---------------------------------------------------------------------------
__global__ __launch_bounds__(256)
void transpose_kernel(const float* __restrict__ src, float* __restrict__ dst,
                      int lds, int ldd,
                      int nh, long sSb, long sSh, long sDb, long sDh)
{
    __shared__ float t[32][33];
    const int bz = blockIdx.z;
    const int bb = bz / nh;
    const int hh = bz - bb * nh;
    src += (long)bb * sSb + (long)hh * sSh;
    dst += (long)bb * sDb + (long)hh * sDh;

    const int bx = blockIdx.x * 32;   // C dim
    const int by = blockIdx.y * 32;   // R dim
    const int tx = threadIdx.x & 31;
    const int ty = threadIdx.x >> 5;  // 0..7

    #pragma unroll
    for (int jj = 0; jj < 4; jj++)
        t[ty + 8 * jj][tx] = roundtf32(src[(size_t)(by + ty + 8 * jj) * lds + bx + tx]);
    __syncthreads();
    #pragma unroll
    for (int jj = 0; jj < 4; jj++)
        dst[(size_t)(bx + ty + 8 * jj) * ldd + by + tx] = t[tx][ty + 8 * jj];
}

// Elementwise tf32 rounding pass (for x)
__global__ __launch_bounds__(256)
void round_kernel(const float* __restrict__ src, float* __restrict__ dst, int n4)
{
    int i = blockIdx.x * 256 + threadIdx.x;
    if (i < n4) {
        float4 v = reinterpret_cast<const float4*>(src)[i];
        v.x = roundtf32(v.x); v.y = roundtf32(v.y);
        v.z = roundtf32(v.z); v.w = roundtf32(v.w);
        reinterpret_cast<float4*>(dst)[i] = v;
    }
}

// ---------------------------------------------------------------------------
// Row softmax over rows of length TT; writes tf32-rounded probabilities.
// ---------------------------------------------------------------------------
__global__ __launch_bounds__(256, 2)
void softmax_kernel(float* __restrict__ att)
{
    float* row = att + (size_t)blockIdx.x * TT;
    const int tid = threadIdx.x;
    float v[8];
    float mx = -1e30f;
    #pragma unroll
    for (int i = 0; i < 8; i++) {
        v[i] = row[tid + (i << 8)];
        mx = fmaxf(mx, v[i]);
    }
    __shared__ float red[32];
    #pragma unroll
    for (int o = 16; o > 0; o >>= 1)
        mx = fmaxf(mx, __shfl_xor_sync(0xffffffffu, mx, o));
    if ((tid & 31) == 0) red[tid >> 5] = mx;
    __syncthreads();
    if (tid < 32) {
        float m2 = (tid < 8) ? red[tid] : -1e30f;
        #pragma unroll
        for (int o = 4; o > 0; o >>= 1)
            m2 = fmaxf(m2, __shfl_xor_sync(0xffffffffu, m2, o));
        if (tid == 0) red[0] = m2;
    }
    __syncthreads();
    mx = red[0];
    __syncthreads();

    float s = 0.f;
    #pragma unroll
    for (int i = 0; i < 8; i++) {
        v[i] = __expf(v[i] - mx);
        s += v[i];
    }
    #pragma unroll
    for (int o = 16; o > 0; o >>= 1)
        s += __shfl_xor_sync(0xffffffffu, s, o);
    if ((tid & 31) == 0) red[tid >> 5] = s;
    __syncthreads();
    if (tid < 32) {
        float s2 = (tid < 8) ? red[tid] : 0.f;
        #pragma unroll
        for (int o = 4; o > 0; o >>= 1)
            s2 += __shfl_xor_sync(0xffffffffu, s2, o);
        if (tid == 0) red[0] = s2;
    }
    __syncthreads();
    const float inv = 1.f / red[0];
    #pragma unroll
    for (int i = 0; i < 8; i++)
        row[tid + (i << 8)] = roundtf32(v[i] * inv);
}

// ---------------------------------------------------------------------------
extern "C" void kernel_launch(void* const* d_in, const int* in_sizes, int n_in,
                              void* d_out, int out_size)
{
    const float* x  = (const float*)d_in[0];   // [4,2048,768]
    const float* Wq = (const float*)d_in[1];   // [768,6144]
    const float* Wk = (const float*)d_in[2];
    const float* Wv = (const float*)d_in[3];
    const float* Wu = (const float*)d_in[4];   // [6144,768]
    const float* bu = (const float*)d_in[5];   // [768]
    float* out = (float*)d_out;                // [8192,768]

    float *gx, *qkv, *wt, *att, *vt, *ho;
    cudaGetSymbolAddress((void**)&gx,  g_x);
    cudaGetSymbolAddress((void**)&qkv, g_qkv);
    cudaGetSymbolAddress((void**)&wt,  g_wt);
    cudaGetSymbolAddress((void**)&att, g_att);
    cudaGetSymbolAddress((void**)&vt,  g_vt);
    cudaGetSymbolAddress((void**)&ho,  g_ho);

    float* q = qkv;
    float* k = qkv + (size_t)MR * HE;
    float* v = qkv + (size_t)2 * MR * HE;
    const long WSZ = (long)HE * EE;

    cudaFuncSetAttribute(tgemm<false, true>,  cudaFuncAttributeMaxDynamicSharedMemorySize, SMEM_TOTAL);
    cudaFuncSetAttribute(tgemm<true,  false>, cudaFuncAttributeMaxDynamicSharedMemorySize, SMEM_TOTAL);

    const dim3 blk(256);
    const dim3 gblk(128);
    const float alpha_scores = 1.0f / sqrtf((float)EE);

    // 0) preprocessing: round x; transpose+round weights -> K-major [N,K]
    round_kernel<<<(MR * EE / 4 + 255) / 256, blk>>>(x, gx, MR * EE / 4);
    transpose_kernel<<<dim3(HE/32, EE/32, 1), blk>>>(Wq, wt + 0*WSZ, HE, EE, 1, 0,0,0,0);
    transpose_kernel<<<dim3(HE/32, EE/32, 1), blk>>>(Wk, wt + 1*WSZ, HE, EE, 1, 0,0,0,0);
    transpose_kernel<<<dim3(HE/32, EE/32, 1), blk>>>(Wv, wt + 2*WSZ, HE, EE, 1, 0,0,0,0);
    transpose_kernel<<<dim3(EE/32, HE/32, 1), blk>>>(Wu, wt + 3*WSZ, EE, HE, 1, 0,0,0,0);

    // 1) QKV projections (batched z=3): qkv[z] = x @ W[z]^T-layout -> [8192,6144]
    tgemm<false, true><<<dim3(HE/128, MR/128, 3), gblk, SMEM_TOTAL>>>(
        gx, wt, nullptr, qkv,
        EE, EE, EE, HE,
        1, 0, 0, WSZ, 0, (long)MR * HE, 0, 1.f);

    // 2) transpose v -> vt [b,h,e,t]  (already tf32; rounding is idempotent)
    transpose_kernel<<<dim3(EE/32, TT/32, BB*HH), blk>>>(
        v, vt, HE, TT,
        HH, (long)TT * HE, (long)EE, (long)HH * EE * TT, (long)EE * TT);

    // 3) scores: att[b,h] = alpha * q_bh @ k_bh^T
    tgemm<false, true><<<dim3(TT/128, TT/128, BB*HH), gblk, SMEM_TOTAL>>>(
        q, k, nullptr, att,
        EE, HE, HE, TT,
        HH, (long)TT * HE, (long)EE, (long)TT * HE, (long)EE,
        (long)HH * TT * TT, (long)TT * TT, alpha_scores);

    // 4) softmax (writes tf32-rounded)
    softmax_kernel<<<BB * HH * TT, blk>>>(att);

    // 5) O = att @ vt^T  -> ho [b,t,h,e]
    tgemm<false, true><<<dim3(EE/128, TT/128, BB*HH), gblk, SMEM_TOTAL>>>(
        att, vt, nullptr, ho,
        TT, TT, TT, HE,
        HH, (long)HH * TT * TT, (long)TT * TT,
        (long)HH * EE * TT, (long)EE * TT,
        (long)TT * HE, (long)EE, 1.f);

    // 6) output projection + bias (B = WuT); final output NOT rounded
    tgemm<true, false><<<dim3(EE/128, MR/128, 1), gblk, SMEM_TOTAL>>>(
        ho, wt + 3*WSZ, bu, out,
        HE, HE, HE, EE,
        1, 0, 0, 0, 0, 0, 0, 1.f);
}

// round 7
// speedup vs baseline: 7.7511x; 1.8409x over previous
#include <cuda_runtime.h>
#include <cuda_fp16.h>
#include <math.h>
#include <stdint.h>

// Problem shape (fixed by the reference)
#define BB 4
#define TT 2048
#define EE 768
#define HH 8
#define HE 6144          // H*E
#define MR 8192          // B*T

// Scratch (allocation-free rule -> __device__ globals)
__device__ __half g_x16[(size_t)MR * EE];                 // x in fp16
__device__ __half g_w16[(size_t)4 * HE * EE];             // WqT|WkT|WvT|WuT fp16
__device__ __half g_qkv[(size_t)3 * MR * HE];             // q|k|v fp16
__device__ float  g_attf[(size_t)BB * HH * (size_t)TT * TT];  // logits fp32
__device__ __half g_att16[(size_t)BB * HH * (size_t)TT * TT]; // probs fp16
__device__ __half g_vt[(size_t)MR * HE];                  // v^T per (b,h): [b,h,e,t]
__device__ __half g_ho[(size_t)MR * HE];                  // attention out fp16

// Tiling: CTA 128x128, BK=64 halfs (128B rows). 4 warps, warp tile 64x64.
#define LDH 72                          // padded stride in halfs (144 B rows)
#define TILE_HALFS (128 * LDH)          // 9216
#define TILE_BYTES (TILE_HALFS * 2)     // 18432
#define SMEM_TOTAL (4 * TILE_BYTES)     // A0,A1,B0,B1 = 73728 B
#define BKH 64

__device__ __forceinline__ void cp_async16(void* smem_dst, const void* gmem_src) {
    uint32_t s = (uint32_t)__cvta_generic_to_shared(smem_dst);
    asm volatile("cp.async.cg.shared.global [%0], [%1], 16;" :: "r"(s), "l"(gmem_src));
}
__device__ __forceinline__ void cp_commit() { asm volatile("cp.async.commit_group;" ::: "memory"); }
template<int N>
__device__ __forceinline__ void cp_wait() { asm volatile("cp.async.wait_group %0;" :: "n"(N) : "memory"); }
__device__ __forceinline__ void ldsm_x4(uint32_t (&d)[4], uint32_t addr) {
    asm volatile("ldmatrix.sync.aligned.m8n8.x4.shared.b16 {%0,%1,%2,%3}, [%4];"
        : "=r"(d[0]), "=r"(d[1]), "=r"(d[2]), "=r"(d[3]) : "r"(addr));
}

// ---------------------------------------------------------------------------
// fp16 tensor-core GEMM (m16n8k16). C = alpha * A[M,K] @ B[N,K]^T (+bias).
// A, B fp16 K-major in gmem. C fp32 or fp16. Batched (b,h) strides.
// 4 warps (128 thr), warp tile 64x64: per K-tile 32 LDSM : 128 HMMA.
// ---------------------------------------------------------------------------
template<bool OUT_HALF, bool BIAS>
__global__ __launch_bounds__(128, 2)
void hgemm(const __half* __restrict__ A, const __half* __restrict__ B,
           const float* __restrict__ bias, void* __restrict__ Cv,
           int K, int lda, int ldb, int ldc,
           int nh, long sAb, long sAh, long sBb, long sBh,
           long sCb, long sCh, float alpha)
{
    extern __shared__ __half smem[];
    const uint32_t smem_u = (uint32_t)__cvta_generic_to_shared(smem);

    const int bz = blockIdx.z;
    const int bb = bz / nh;
    const int hh = bz - bb * nh;
    A += (long)bb * sAb + (long)hh * sAh;
    B += (long)bb * sBb + (long)hh * sBh;
    float*  Cf = (float*)Cv  + bb * sCb + hh * sCh;
    __half* Ch = (__half*)Cv + bb * sCb + hh * sCh;

    const int tid  = threadIdx.x;
    const int warp = tid >> 5, lane = tid & 31;
    const int g    = lane >> 2, tig = lane & 3;
    const int r8   = lane & 7, j = lane >> 3;      // LDSM lane roles
    const int wm   = (warp >> 1) * 64;   // 2 warps along M
    const int wn   = (warp & 1)  * 64;   // 2 warps along N
    const int row0 = blockIdx.y * 128;
    const int col0 = blockIdx.x * 128;

    // LDSM byte offsets within a tile buffer (+kf*32 bytes per k16 step)
    // A blocks: j0=(m0-7,k0-7) j1=(m8-15,k0-7) j2=(m0-7,k8-15) j3=(m8-15,k8-15)
    uint32_t aoff[4], boff[4];
    #pragma unroll
    for (int mi = 0; mi < 4; mi++)
        aoff[mi] = ((wm + mi * 16 + (j & 1) * 8 + r8) * LDH + (j >> 1) * 8) * 2;
    // B blocks: j0=(n0-7,k0-7) j1=(n0-7,k8-15) j2=(n8-15,k0-7) j3=(n8-15,k8-15)
    #pragma unroll
    for (int p = 0; p < 4; p++)
        boff[p] = ((wn + p * 16 + (j >> 1) * 8 + r8) * LDH + (j & 1) * 8) * 2;

    float acc[4][8][4] = {};  // [mi][ni][reg]

    // Loader: tiles are 128 rows x 64 halfs (8 x 16B chunks per row).
    #define LOAD_TILE(K0, BUF)                                                        \
    {                                                                                 \
        __half* as_ = smem + (BUF) * TILE_HALFS;                                      \
        __half* bs_ = smem + (2 + (BUF)) * TILE_HALFS;                                \
        _Pragma("unroll")                                                             \
        for (int p = 0; p < 8; p++) {                                                 \
            int id = p * 128 + tid;                                                   \
            int rr = id >> 3, kc = (id & 7) << 3;                                     \
            cp_async16(&as_[rr * LDH + kc],                                           \
                       &A[(size_t)(row0 + rr) * lda + (K0) + kc]);                    \
        }                                                                             \
        _Pragma("unroll")                                                             \
        for (int p = 0; p < 8; p++) {                                                 \
            int id = p * 128 + tid;                                                   \
            int rr = id >> 3, kc = (id & 7) << 3;                                     \
            cp_async16(&bs_[rr * LDH + kc],                                           \
                       &B[(size_t)(col0 + rr) * ldb + (K0) + kc]);                    \
        }                                                                             \
        cp_commit();                                                                  \
    }

    LOAD_TILE(0, 0);
    const int ntiles = K / BKH;

    for (int kt = 0; kt < ntiles; kt++) {
        const int buf = kt & 1;
        if (kt + 1 < ntiles) {
            LOAD_TILE((kt + 1) * BKH, buf ^ 1);
            cp_wait<1>();
        } else {
            cp_wait<0>();
        }
        __syncthreads();

        const uint32_t as_u = smem_u + buf * TILE_BYTES;
        const uint32_t bs_u = smem_u + (2 + buf) * TILE_BYTES;

        #pragma unroll
        for (int kf = 0; kf < 4; kf++) {          // 4 x k16 steps
            uint32_t af[4][4];
            #pragma unroll
            for (int mi = 0; mi < 4; mi++)
                ldsm_x4(af[mi], as_u + aoff[mi] + kf * 32);
            uint32_t bf[4][4];
            #pragma unroll
            for (int p = 0; p < 4; p++)
                ldsm_x4(bf[p], bs_u + boff[p] + kf * 32);

            #pragma unroll
            for (int mi = 0; mi < 4; mi++)
                #pragma unroll
                for (int ni = 0; ni < 8; ni++) {
                    const uint32_t b0 = bf[ni >> 1][(ni & 1) * 2 + 0];
                    const uint32_t b1 = bf[ni >> 1][(ni & 1) * 2 + 1];
                    asm volatile(
                        "mma.sync.aligned.m16n8k16.row.col.f32.f16.f16.f32 "
                        "{%0,%1,%2,%3},{%4,%5,%6,%7},{%8,%9},{%0,%1,%2,%3};"
                        : "+f"(acc[mi][ni][0]), "+f"(acc[mi][ni][1]),
                          "+f"(acc[mi][ni][2]), "+f"(acc[mi][ni][3])
                        : "r"(af[mi][0]), "r"(af[mi][1]), "r"(af[mi][2]), "r"(af[mi][3]),
                          "r"(b0), "r"(b1));
                }
        }
        __syncthreads();
    }

    // Epilogue
    #pragma unroll
    for (int mi = 0; mi < 4; mi++) {
        const int r = row0 + wm + mi * 16 + g;
        #pragma unroll
        for (int ni = 0; ni < 8; ni++) {
            const int c = col0 + wn + ni * 8 + tig * 2;
            float2 v0 = make_float2(alpha * acc[mi][ni][0], alpha * acc[mi][ni][1]);
            float2 v1 = make_float2(alpha * acc[mi][ni][2], alpha * acc[mi][ni][3]);
            if (BIAS) {
                const float b0 = bias[c], b1 = bias[c + 1];
                v0.x += b0; v0.y += b1; v1.x += b0; v1.y += b1;
            }
            if (OUT_HALF) {
                *reinterpret_cast<__half2*>(&Ch[(size_t)r * ldc + c]) =
                    __floats2half2_rn(v0.x, v0.y);
                *reinterpret_cast<__half2*>(&Ch[(size_t)(r + 8) * ldc + c]) =
                    __floats2half2_rn(v1.x, v1.y);
            } else {
                *reinterpret_cast<float2*>(&Cf[(size_t)r * ldc + c])       = v0;
                *reinterpret_cast<float2*>(&Cf[(size_t)(r + 8) * ldc + c]) = v1;
            }
        }
    }
    #undef LOAD_TILE
}

// ---------------------------------------------------------------------------
// float->half transpose: dst[c][r] = half(src[r][c])
// ---------------------------------------------------------------------------
__global__ __launch_bounds__(256)
void transpose_f2h(const float* __restrict__ src, __half* __restrict__ dst,
                   int lds, int ldd)
{
    __shared__ float t[32][33];
    const int bx = blockIdx.x * 32;   // C dim
    const int by = blockIdx.y * 32;   // R dim
    const int tx = threadIdx.x & 31;
    const int ty = threadIdx.x >> 5;

    #pragma unroll
    for (int jj = 0; jj < 4; jj++)
        t[ty + 8 * jj][tx] = src[(size_t)(by + ty + 8 * jj) * lds + bx + tx];
    __syncthreads();
    #pragma unroll
    for (int jj = 0; jj < 4; jj++)
        dst[(size_t)(bx + ty + 8 * jj) * ldd + by + tx] = __float2half_rn(t[tx][ty + 8 * jj]);
}

// half->half transpose, batched (for v -> vt)
__global__ __launch_bounds__(256)
void transpose_h2h(const __half* __restrict__ src, __half* __restrict__ dst,
                   int lds, int ldd,
                   int nh, long sSb, long sSh, long sDb, long sDh)
{
    __shared__ __half t[32][34];
    const int bz = blockIdx.z;
    const int bb = bz / nh;
    const int hh = bz - bb * nh;
    src += (long)bb * sSb + (long)hh * sSh;
    dst += (long)bb * sDb + (long)hh * sDh;

    const int bx = blockIdx.x * 32;
    const int by = blockIdx.y * 32;
    const int tx = threadIdx.x & 31;
    const int ty = threadIdx.x >> 5;

    #pragma unroll
    for (int jj = 0; jj < 4; jj++)
        t[ty + 8 * jj][tx] = src[(size_t)(by + ty + 8 * jj) * lds + bx + tx];
    __syncthreads();
    #pragma unroll
    for (int jj = 0; jj < 4; jj++)
        dst[(size_t)(bx + ty + 8 * jj) * ldd + by + tx] = t[tx][ty + 8 * jj];
}

// Elementwise float -> half
__global__ __launch_bounds__(256)
void f2h_kernel(const float* __restrict__ src, __half* __restrict__ dst, int n4)
{
    int i = blockIdx.x * 256 + threadIdx.x;
    if (i < n4) {
        float4 v = reinterpret_cast<const float4*>(src)[i];
        __half2 h0 = __floats2half2_rn(v.x, v.y);
        __half2 h1 = __floats2half2_rn(v.z, v.w);
        reinterpret_cast<__half2*>(dst)[2 * i]     = h0;
        reinterpret_cast<__half2*>(dst)[2 * i + 1] = h1;
    }
}

// ---------------------------------------------------------------------------
// Row softmax: reads fp32 logits, writes fp16 probabilities.
// ---------------------------------------------------------------------------
__global__ __launch_bounds__(256, 2)
void softmax_kernel(const float* __restrict__ attf, __half* __restrict__ att16)
{
    const float* row = attf + (size_t)blockIdx.x * TT;
    __half* orow = att16 + (size_t)blockIdx.x * TT;
    const int tid = threadIdx.x;
    float v[8];
    float mx = -1e30f;
    #pragma unroll
    for (int i = 0; i < 8; i++) {
        v[i] = row[tid + (i << 8)];
        mx = fmaxf(mx, v[i]);
    }
    __shared__ float red[32];
    #pragma unroll
    for (int o = 16; o > 0; o >>= 1)
        mx = fmaxf(mx, __shfl_xor_sync(0xffffffffu, mx, o));
    if ((tid & 31) == 0) red[tid >> 5] = mx;
    __syncthreads();
    if (tid < 32) {
        float m2 = (tid < 8) ? red[tid] : -1e30f;
        #pragma unroll
        for (int o = 4; o > 0; o >>= 1)
            m2 = fmaxf(m2, __shfl_xor_sync(0xffffffffu, m2, o));
        if (tid == 0) red[0] = m2;
    }
    __syncthreads();
    mx = red[0];
    __syncthreads();

    float s = 0.f;
    #pragma unroll
    for (int i = 0; i < 8; i++) {
        v[i] = __expf(v[i] - mx);
        s += v[i];
    }
    #pragma unroll
    for (int o = 16; o > 0; o >>= 1)
        s += __shfl_xor_sync(0xffffffffu, s, o);
    if ((tid & 31) == 0) red[tid >> 5] = s;
    __syncthreads();
    if (tid < 32) {
        float s2 = (tid < 8) ? red[tid] : 0.f;
        #pragma unroll
        for (int o = 4; o > 0; o >>= 1)
            s2 += __shfl_xor_sync(0xffffffffu, s2, o);
        if (tid == 0) red[0] = s2;
    }
    __syncthreads();
    const float inv = 1.f / red[0];
    #pragma unroll
    for (int i = 0; i < 8; i++)
        orow[tid + (i << 8)] = __float2half_rn(v[i] * inv);
}

// ---------------------------------------------------------------------------
extern "C" void kernel_launch(void* const* d_in, const int* in_sizes, int n_in,
                              void* d_out, int out_size)
{
    const float* x  = (const float*)d_in[0];   // [4,2048,768]
    const float* Wq = (const float*)d_in[1];   // [768,6144]
    const float* Wk = (const float*)d_in[2];
    const float* Wv = (const float*)d_in[3];
    const float* Wu = (const float*)d_in[4];   // [6144,768]
    const float* bu = (const float*)d_in[5];   // [768]
    float* out = (float*)d_out;                // [8192,768]

    __half *x16, *w16, *qkv, *att16, *vt, *ho;
    float *attf;
    cudaGetSymbolAddress((void**)&x16,   g_x16);
    cudaGetSymbolAddress((void**)&w16,   g_w16);
    cudaGetSymbolAddress((void**)&qkv,   g_qkv);
    cudaGetSymbolAddress((void**)&attf,  g_attf);
    cudaGetSymbolAddress((void**)&att16, g_att16);
    cudaGetSymbolAddress((void**)&vt,    g_vt);
    cudaGetSymbolAddress((void**)&ho,    g_ho);

    __half* q = qkv;
    __half* k = qkv + (size_t)MR * HE;
    __half* v = qkv + (size_t)2 * MR * HE;
    const long WSZ = (long)HE * EE;

    cudaFuncSetAttribute(hgemm<true,  false>, cudaFuncAttributeMaxDynamicSharedMemorySize, SMEM_TOTAL);
    cudaFuncSetAttribute(hgemm<false, false>, cudaFuncAttributeMaxDynamicSharedMemorySize, SMEM_TOTAL);
    cudaFuncSetAttribute(hgemm<false, true >, cudaFuncAttributeMaxDynamicSharedMemorySize, SMEM_TOTAL);

    const dim3 blk(256);
    const dim3 gblk(128);
    const float alpha_scores = 1.0f / sqrtf((float)EE);

    // 0) preprocessing: x -> fp16; weights transpose -> K-major [N,K] fp16
    f2h_kernel<<<(MR * EE / 4 + 255) / 256, blk>>>(x, x16, MR * EE / 4);
    transpose_f2h<<<dim3(HE/32, EE/32, 1), blk>>>(Wq, w16 + 0*WSZ, HE, EE);
    transpose_f2h<<<dim3(HE/32, EE/32, 1), blk>>>(Wk, w16 + 1*WSZ, HE, EE);
    transpose_f2h<<<dim3(HE/32, EE/32, 1), blk>>>(Wv, w16 + 2*WSZ, HE, EE);
    transpose_f2h<<<dim3(EE/32, HE/32, 1), blk>>>(Wu, w16 + 3*WSZ, EE, HE);

    // 1) QKV projections (batched z=3): qkv[z] = x @ W[z] -> fp16 [8192,6144]
    hgemm<true, false><<<dim3(HE/128, MR/128, 3), gblk, SMEM_TOTAL>>>(
        x16, w16, nullptr, qkv,
        EE, EE, EE, HE,
        1, 0, 0, WSZ, 0, (long)MR * HE, 0, 1.f);

    // 2) transpose v -> vt [b,h,e,t]
    transpose_h2h<<<dim3(EE/32, TT/32, BB*HH), blk>>>(
        v, vt, HE, TT,
        HH, (long)TT * HE, (long)EE, (long)HH * EE * TT, (long)EE * TT);

    // 3) scores: attf[b,h] = alpha * q_bh @ k_bh^T  -> fp32 logits
    hgemm<false, false><<<dim3(TT/128, TT/128, BB*HH), gblk, SMEM_TOTAL>>>(
        q, k, nullptr, attf,
        EE, HE, HE, TT,
        HH, (long)TT * HE, (long)EE, (long)TT * HE, (long)EE,
        (long)HH * TT * TT, (long)TT * TT, alpha_scores);

    // 4) softmax: fp32 logits -> fp16 probs
    softmax_kernel<<<BB * HH * TT, blk>>>(attf, att16);

    // 5) O = att @ v -> ho fp16 [b,t,h,e]
    hgemm<true, false><<<dim3(EE/128, TT/128, BB*HH), gblk, SMEM_TOTAL>>>(
        att16, vt, nullptr, ho,
        TT, TT, TT, HE,
        HH, (long)HH * TT * TT, (long)TT * TT,
        (long)HH * EE * TT, (long)EE * TT,
        (long)TT * HE, (long)EE, 1.f);

    // 6) output projection + bias -> fp32 out
    hgemm<false, true><<<dim3(EE/128, MR/128, 1), gblk, SMEM_TOTAL>>>(
        ho, w16 + 3*WSZ, bu, out,
        HE, HE, HE, EE,
        1, 0, 0, 0, 0, 0, 0, 1.f);
}

// round 8
// speedup vs baseline: 8.0502x; 1.0386x over previous
#include <cuda_runtime.h>
#include <cuda_fp16.h>
#include <math.h>
#include <stdint.h>

// Problem shape (fixed by the reference)
#define BB 4
#define TT 2048
#define EE 768
#define HH 8
#define HE 6144          // H*E
#define MR 8192          // B*T

// Scratch (allocation-free rule -> __device__ globals)
__device__ __half g_x16[(size_t)MR * EE];                 // x in fp16
__device__ __half g_w16[(size_t)4 * HE * EE];             // WqT|WkT|WvT|WuT fp16
__device__ __half g_qkv[(size_t)3 * MR * HE];             // q|k|v fp16
__device__ __half g_p16[(size_t)BB * HH * (size_t)TT * TT]; // unnormalized exp(logit) fp16
__device__ float  g_rowsum[(size_t)BB * HH * TT];         // per-row sum of exp
__device__ __half g_vt[(size_t)MR * HE];                  // v^T per (b,h): [b,h,e,t]
__device__ __half g_ho[(size_t)MR * HE];                  // attention out fp16

// Tiling: CTA 128x128, BK=64 halfs (128B rows). 4 warps, warp tile 64x64.
#define LDH 72                          // padded stride in halfs (144 B rows)
#define TILE_HALFS (128 * LDH)          // 9216
#define TILE_BYTES (TILE_HALFS * 2)     // 18432
#define SMEM_TOTAL (4 * TILE_BYTES)     // A0,A1,B0,B1 = 73728 B
#define BKH 64

__device__ __forceinline__ void cp_async16(void* smem_dst, const void* gmem_src) {
    uint32_t s = (uint32_t)__cvta_generic_to_shared(smem_dst);
    asm volatile("cp.async.cg.shared.global [%0], [%1], 16;" :: "r"(s), "l"(gmem_src));
}
__device__ __forceinline__ void cp_commit() { asm volatile("cp.async.commit_group;" ::: "memory"); }
template<int N>
__device__ __forceinline__ void cp_wait() { asm volatile("cp.async.wait_group %0;" :: "n"(N) : "memory"); }
__device__ __forceinline__ void ldsm_x4(uint32_t (&d)[4], uint32_t addr) {
    asm volatile("ldmatrix.sync.aligned.m8n8.x4.shared.b16 {%0,%1,%2,%3}, [%4];"
        : "=r"(d[0]), "=r"(d[1]), "=r"(d[2]), "=r"(d[3]) : "r"(addr));
}

// ---------------------------------------------------------------------------
// fp16 tensor-core GEMM (m16n8k16). C = alpha * A[M,K] @ B[N,K]^T (+bias).
// MODE: 0 = fp16 out, 1 = fp32 out (+bias), 2 = EXPSUM (p=exp(alpha*acc),
//       fp16 out, atomic per-row sums), 3 = NORM (fp16 out / rowsum[row]).
// 4 warps (128 thr), warp tile 64x64: per K-tile 32 LDSM : 128 HMMA.
// ---------------------------------------------------------------------------
template<int MODE, bool BIAS>
__global__ __launch_bounds__(128, 2)
void hgemm(const __half* __restrict__ A, const __half* __restrict__ B,
           const float* __restrict__ bias, void* __restrict__ Cv,
           float* __restrict__ rowsum,
           int K, int lda, int ldb, int ldc,
           int nh, long sAb, long sAh, long sBb, long sBh,
           long sCb, long sCh, float alpha)
{
    extern __shared__ __half smem[];
    const uint32_t smem_u = (uint32_t)__cvta_generic_to_shared(smem);

    const int bz = blockIdx.z;
    const int bb = bz / nh;
    const int hh = bz - bb * nh;
    A += (long)bb * sAb + (long)hh * sAh;
    B += (long)bb * sBb + (long)hh * sBh;
    float*  Cf = (float*)Cv  + bb * sCb + hh * sCh;
    __half* Ch = (__half*)Cv + bb * sCb + hh * sCh;
    if (MODE == 2 || MODE == 3) rowsum += (long)bz * TT;

    const int tid  = threadIdx.x;
    const int warp = tid >> 5, lane = tid & 31;
    const int g    = lane >> 2, tig = lane & 3;
    const int r8   = lane & 7, j = lane >> 3;      // LDSM lane roles
    const int wm   = (warp >> 1) * 64;   // 2 warps along M
    const int wn   = (warp & 1)  * 64;   // 2 warps along N
    const int row0 = blockIdx.y * 128;
    const int col0 = blockIdx.x * 128;

    // LDSM byte offsets within a tile buffer (+kf*32 bytes per k16 step)
    uint32_t aoff[4], boff[4];
    #pragma unroll
    for (int mi = 0; mi < 4; mi++)
        aoff[mi] = ((wm + mi * 16 + (j & 1) * 8 + r8) * LDH + (j >> 1) * 8) * 2;
    #pragma unroll
    for (int p = 0; p < 4; p++)
        boff[p] = ((wn + p * 16 + (j >> 1) * 8 + r8) * LDH + (j & 1) * 8) * 2;

    float acc[4][8][4] = {};  // [mi][ni][reg]

    // Loader: tiles are 128 rows x 64 halfs (8 x 16B chunks per row).
    #define LOAD_TILE(K0, BUF)                                                        \
    {                                                                                 \
        __half* as_ = smem + (BUF) * TILE_HALFS;                                      \
        __half* bs_ = smem + (2 + (BUF)) * TILE_HALFS;                                \
        _Pragma("unroll")                                                             \
        for (int p = 0; p < 8; p++) {                                                 \
            int id = p * 128 + tid;                                                   \
            int rr = id >> 3, kc = (id & 7) << 3;                                     \
            cp_async16(&as_[rr * LDH + kc],                                           \
                       &A[(size_t)(row0 + rr) * lda + (K0) + kc]);                    \
        }                                                                             \
        _Pragma("unroll")                                                             \
        for (int p = 0; p < 8; p++) {                                                 \
            int id = p * 128 + tid;                                                   \
            int rr = id >> 3, kc = (id & 7) << 3;                                     \
            cp_async16(&bs_[rr * LDH + kc],                                           \
                       &B[(size_t)(col0 + rr) * ldb + (K0) + kc]);                    \
        }                                                                             \
        cp_commit();                                                                  \
    }

    LOAD_TILE(0, 0);
    const int ntiles = K / BKH;

    for (int kt = 0; kt < ntiles; kt++) {
        const int buf = kt & 1;
        if (kt + 1 < ntiles) {
            LOAD_TILE((kt + 1) * BKH, buf ^ 1);
            cp_wait<1>();
        } else {
            cp_wait<0>();
        }
        __syncthreads();

        const uint32_t as_u = smem_u + buf * TILE_BYTES;
        const uint32_t bs_u = smem_u + (2 + buf) * TILE_BYTES;

        #pragma unroll
        for (int kf = 0; kf < 4; kf++) {          // 4 x k16 steps
            uint32_t af[4][4];
            #pragma unroll
            for (int mi = 0; mi < 4; mi++)
                ldsm_x4(af[mi], as_u + aoff[mi] + kf * 32);
            uint32_t bf[4][4];
            #pragma unroll
            for (int p = 0; p < 4; p++)
                ldsm_x4(bf[p], bs_u + boff[p] + kf * 32);

            #pragma unroll
            for (int mi = 0; mi < 4; mi++)
                #pragma unroll
                for (int ni = 0; ni < 8; ni++) {
                    const uint32_t b0 = bf[ni >> 1][(ni & 1) * 2 + 0];
                    const uint32_t b1 = bf[ni >> 1][(ni & 1) * 2 + 1];
                    asm volatile(
                        "mma.sync.aligned.m16n8k16.row.col.f32.f16.f16.f32 "
                        "{%0,%1,%2,%3},{%4,%5,%6,%7},{%8,%9},{%0,%1,%2,%3};"
                        : "+f"(acc[mi][ni][0]), "+f"(acc[mi][ni][1]),
                          "+f"(acc[mi][ni][2]), "+f"(acc[mi][ni][3])
                        : "r"(af[mi][0]), "r"(af[mi][1]), "r"(af[mi][2]), "r"(af[mi][3]),
                          "r"(b0), "r"(b1));
                }
        }
        __syncthreads();
    }

    // Epilogue
    #pragma unroll
    for (int mi = 0; mi < 4; mi++) {
        const int r = row0 + wm + mi * 16 + g;

        float inv0 = 1.f, inv1 = 1.f;
        if (MODE == 3) {
            inv0 = 1.0f / rowsum[r];
            inv1 = 1.0f / rowsum[r + 8];
        }
        float s0 = 0.f, s1 = 0.f;   // EXPSUM partial row sums

        #pragma unroll
        for (int ni = 0; ni < 8; ni++) {
            const int c = col0 + wn + ni * 8 + tig * 2;
            float v0x = acc[mi][ni][0], v0y = acc[mi][ni][1];
            float v1x = acc[mi][ni][2], v1y = acc[mi][ni][3];

            if (MODE == 2) {
                // p = exp(alpha_orig * acc); alpha passed pre-multiplied by log2(e)
                v0x = exp2f(alpha * v0x); v0y = exp2f(alpha * v0y);
                v1x = exp2f(alpha * v1x); v1y = exp2f(alpha * v1y);
                s0 += v0x + v0y; s1 += v1x + v1y;
            } else if (MODE == 3) {
                v0x *= inv0; v0y *= inv0; v1x *= inv1; v1y *= inv1;
            } else {
                v0x *= alpha; v0y *= alpha; v1x *= alpha; v1y *= alpha;
            }
            if (BIAS) {
                const float b0 = bias[c], b1 = bias[c + 1];
                v0x += b0; v0y += b1; v1x += b0; v1y += b1;
            }
            if (MODE == 1) {
                *reinterpret_cast<float2*>(&Cf[(size_t)r * ldc + c]) = make_float2(v0x, v0y);
                *reinterpret_cast<float2*>(&Cf[(size_t)(r + 8) * ldc + c]) = make_float2(v1x, v1y);
            } else {
                *reinterpret_cast<__half2*>(&Ch[(size_t)r * ldc + c]) =
                    __floats2half2_rn(v0x, v0y);
                *reinterpret_cast<__half2*>(&Ch[(size_t)(r + 8) * ldc + c]) =
                    __floats2half2_rn(v1x, v1y);
            }
        }

        if (MODE == 2) {
            // reduce over the 4 lanes (tig) sharing each row, then one atomic
            s0 += __shfl_xor_sync(0xffffffffu, s0, 1);
            s0 += __shfl_xor_sync(0xffffffffu, s0, 2);
            s1 += __shfl_xor_sync(0xffffffffu, s1, 1);
            s1 += __shfl_xor_sync(0xffffffffu, s1, 2);
            if (tig == 0) {
                atomicAdd(&rowsum[r], s0);
                atomicAdd(&rowsum[r + 8], s1);
            }
        }
    }
    #undef LOAD_TILE
}

// ---------------------------------------------------------------------------
// float->half transpose: dst[c][r] = half(src[r][c])
// ---------------------------------------------------------------------------
__global__ __launch_bounds__(256)
void transpose_f2h(const float* __restrict__ src, __half* __restrict__ dst,
                   int lds, int ldd)
{
    __shared__ float t[32][33];
    const int bx = blockIdx.x * 32;
    const int by = blockIdx.y * 32;
    const int tx = threadIdx.x & 31;
    const int ty = threadIdx.x >> 5;

    #pragma unroll
    for (int jj = 0; jj < 4; jj++)
        t[ty + 8 * jj][tx] = src[(size_t)(by + ty + 8 * jj) * lds + bx + tx];
    __syncthreads();
    #pragma unroll
    for (int jj = 0; jj < 4; jj++)
        dst[(size_t)(bx + ty + 8 * jj) * ldd + by + tx] = __float2half_rn(t[tx][ty + 8 * jj]);
}

// half->half transpose, batched (for v -> vt)
__global__ __launch_bounds__(256)
void transpose_h2h(const __half* __restrict__ src, __half* __restrict__ dst,
                   int lds, int ldd,
                   int nh, long sSb, long sSh, long sDb, long sDh)
{
    __shared__ __half t[32][34];
    const int bz = blockIdx.z;
    const int bb = bz / nh;
    const int hh = bz - bb * nh;
    src += (long)bb * sSb + (long)hh * sSh;
    dst += (long)bb * sDb + (long)hh * sDh;

    const int bx = blockIdx.x * 32;
    const int by = blockIdx.y * 32;
    const int tx = threadIdx.x & 31;
    const int ty = threadIdx.x >> 5;

    #pragma unroll
    for (int jj = 0; jj < 4; jj++)
        t[ty + 8 * jj][tx] = src[(size_t)(by + ty + 8 * jj) * lds + bx + tx];
    __syncthreads();
    #pragma unroll
    for (int jj = 0; jj < 4; jj++)
        dst[(size_t)(bx + ty + 8 * jj) * ldd + by + tx] = t[tx][ty + 8 * jj];
}

// Elementwise float -> half
__global__ __launch_bounds__(256)
void f2h_kernel(const float* __restrict__ src, __half* __restrict__ dst, int n4)
{
    int i = blockIdx.x * 256 + threadIdx.x;
    if (i < n4) {
        float4 v = reinterpret_cast<const float4*>(src)[i];
        reinterpret_cast<__half2*>(dst)[2 * i]     = __floats2half2_rn(v.x, v.y);
        reinterpret_cast<__half2*>(dst)[2 * i + 1] = __floats2half2_rn(v.z, v.w);
    }
}

// Zero rowsum (must run before scores every launch/replay)
__global__ __launch_bounds__(256)
void zero_kernel(float* __restrict__ p, int n)
{
    int i = blockIdx.x * 256 + threadIdx.x;
    if (i < n) p[i] = 0.f;
}

// ---------------------------------------------------------------------------
extern "C" void kernel_launch(void* const* d_in, const int* in_sizes, int n_in,
                              void* d_out, int out_size)
{
    const float* x  = (const float*)d_in[0];   // [4,2048,768]
    const float* Wq = (const float*)d_in[1];   // [768,6144]
    const float* Wk = (const float*)d_in[2];
    const float* Wv = (const float*)d_in[3];
    const float* Wu = (const float*)d_in[4];   // [6144,768]
    const float* bu = (const float*)d_in[5];   // [768]
    float* out = (float*)d_out;                // [8192,768]

    __half *x16, *w16, *qkv, *p16, *vt, *ho;
    float *rowsum;
    cudaGetSymbolAddress((void**)&x16,    g_x16);
    cudaGetSymbolAddress((void**)&w16,    g_w16);
    cudaGetSymbolAddress((void**)&qkv,    g_qkv);
    cudaGetSymbolAddress((void**)&p16,    g_p16);
    cudaGetSymbolAddress((void**)&rowsum, g_rowsum);
    cudaGetSymbolAddress((void**)&vt,     g_vt);
    cudaGetSymbolAddress((void**)&ho,     g_ho);

    __half* q = qkv;
    __half* k = qkv + (size_t)MR * HE;
    __half* v = qkv + (size_t)2 * MR * HE;
    const long WSZ = (long)HE * EE;

    cudaFuncSetAttribute(hgemm<0, false>, cudaFuncAttributeMaxDynamicSharedMemorySize, SMEM_TOTAL);
    cudaFuncSetAttribute(hgemm<1, true >, cudaFuncAttributeMaxDynamicSharedMemorySize, SMEM_TOTAL);
    cudaFuncSetAttribute(hgemm<2, false>, cudaFuncAttributeMaxDynamicSharedMemorySize, SMEM_TOTAL);
    cudaFuncSetAttribute(hgemm<3, false>, cudaFuncAttributeMaxDynamicSharedMemorySize, SMEM_TOTAL);

    const dim3 blk(256);
    const dim3 gblk(128);
    // scores: p = exp(logit), logit = acc / sqrt(e). exp2f form:
    const float alpha_exp = 1.4426950408889634f / sqrtf((float)EE);

    // 0) preprocessing
    f2h_kernel<<<(MR * EE / 4 + 255) / 256, blk>>>(x, x16, MR * EE / 4);
    transpose_f2h<<<dim3(HE/32, EE/32, 1), blk>>>(Wq, w16 + 0*WSZ, HE, EE);
    transpose_f2h<<<dim3(HE/32, EE/32, 1), blk>>>(Wk, w16 + 1*WSZ, HE, EE);
    transpose_f2h<<<dim3(HE/32, EE/32, 1), blk>>>(Wv, w16 + 2*WSZ, HE, EE);
    transpose_f2h<<<dim3(EE/32, HE/32, 1), blk>>>(Wu, w16 + 3*WSZ, EE, HE);
    zero_kernel<<<(BB * HH * TT + 255) / 256, blk>>>(rowsum, BB * HH * TT);

    // 1) QKV projections (batched z=3)
    hgemm<0, false><<<dim3(HE/128, MR/128, 3), gblk, SMEM_TOTAL>>>(
        x16, w16, nullptr, qkv, nullptr,
        EE, EE, EE, HE,
        1, 0, 0, WSZ, 0, (long)MR * HE, 0, 1.f);

    // 2) transpose v -> vt [b,h,e,t]
    transpose_h2h<<<dim3(EE/32, TT/32, BB*HH), blk>>>(
        v, vt, HE, TT,
        HH, (long)TT * HE, (long)EE, (long)HH * EE * TT, (long)EE * TT);

    // 3) scores + exp + rowsum: p16[b,h] = exp(alpha * q_bh @ k_bh^T)
    hgemm<2, false><<<dim3(TT/128, TT/128, BB*HH), gblk, SMEM_TOTAL>>>(
        q, k, nullptr, p16, rowsum,
        EE, HE, HE, TT,
        HH, (long)TT * HE, (long)EE, (long)TT * HE, (long)EE,
        (long)HH * TT * TT, (long)TT * TT, alpha_exp);

    // 4) O = (p @ v) / rowsum -> ho fp16 [b,t,h,e]
    hgemm<3, false><<<dim3(EE/128, TT/128, BB*HH), gblk, SMEM_TOTAL>>>(
        p16, vt, nullptr, ho, rowsum,
        TT, TT, TT, HE,
        HH, (long)HH * TT * TT, (long)TT * TT,
        (long)HH * EE * TT, (long)EE * TT,
        (long)TT * HE, (long)EE, 1.f);

    // 5) output projection + bias -> fp32 out
    hgemm<1, true><<<dim3(EE/128, MR/128, 1), gblk, SMEM_TOTAL>>>(
        ho, w16 + 3*WSZ, bu, out, nullptr,
        HE, HE, HE, EE,
        1, 0, 0, 0, 0, 0, 0, 1.f);
}

// round 9
// speedup vs baseline: 9.3378x; 1.1599x over previous
#include <cuda_runtime.h>
#include <cuda_fp16.h>
#include <math.h>
#include <stdint.h>

// Problem shape (fixed by the reference)
#define BB 4
#define TT 2048
#define EE 768
#define HH 8
#define HE 6144          // H*E
#define MR 8192          // B*T
#define NSPLIT 3         // split-K for final projection

// Scratch (allocation-free rule -> __device__ globals)
__device__ __half g_x16[(size_t)MR * EE];                 // x in fp16
__device__ __half g_w16[(size_t)4 * HE * EE];             // WqT|WkT|WvT|WuT fp16
__device__ __half g_qkv[(size_t)3 * MR * HE];             // q|k|v fp16
__device__ __half g_p16[(size_t)BB * HH * (size_t)TT * TT]; // unnormalized exp(logit)
__device__ float  g_rowsum[(size_t)BB * HH * TT];         // per-row sum of exp
__device__ __half g_vt[(size_t)MR * HE];                  // v^T per (b,h): [b,h,e,t]
__device__ __half g_ho[(size_t)MR * HE];                  // attention out fp16
__device__ float  g_psum[(size_t)NSPLIT * MR * EE];       // split-K partials

// Tiling: CTA 128x128, BK=64 halfs (128B rows, XOR swizzle), 3-stage ring.
#define BKH 64
#define STAGE_BYTES 16384               // one operand tile: 128 rows x 128 B
#define NSTAGE 3
#define SMEM_TOTAL (2 * NSTAGE * STAGE_BYTES)   // A stages then B stages = 98304 B

__device__ __forceinline__ void cp_async16(uint32_t smem_dst, const void* gmem_src) {
    asm volatile("cp.async.cg.shared.global [%0], [%1], 16;" :: "r"(smem_dst), "l"(gmem_src));
}
__device__ __forceinline__ void cp_commit() { asm volatile("cp.async.commit_group;" ::: "memory"); }
template<int N>
__device__ __forceinline__ void cp_wait() { asm volatile("cp.async.wait_group %0;" :: "n"(N) : "memory"); }
__device__ __forceinline__ void ldsm_x4(uint32_t (&d)[4], uint32_t addr) {
    asm volatile("ldmatrix.sync.aligned.m8n8.x4.shared.b16 {%0,%1,%2,%3}, [%4];"
        : "=r"(d[0]), "=r"(d[1]), "=r"(d[2]), "=r"(d[3]) : "r"(addr));
}

// ---------------------------------------------------------------------------
// fp16 tensor-core GEMM (m16n8k16). C = alpha * A[M,K] @ B[N,K]^T.
// MODE: 0 = fp16 out (alpha), 1 = fp32 out (alpha), 2 = EXPSUM, 3 = NORM.
// 4 warps, warp tile 64x64. 3-stage cp.async ring, swizzled smem (128B rows).
// ---------------------------------------------------------------------------
template<int MODE>
__global__ __launch_bounds__(128, 2)
void hgemm(const __half* __restrict__ A, const __half* __restrict__ B,
           void* __restrict__ Cv, float* __restrict__ rowsum,
           int K, int lda, int ldb, int ldc,
           int nh, long sAb, long sAh, long sBb, long sBh,
           long sCb, long sCh, float alpha)
{
    extern __shared__ __half smem[];
    const uint32_t smem_u = (uint32_t)__cvta_generic_to_shared(smem);

    const int bz = blockIdx.z;
    const int bb = bz / nh;
    const int hh = bz - bb * nh;
    A += (long)bb * sAb + (long)hh * sAh;
    B += (long)bb * sBb + (long)hh * sBh;
    float*  Cf = (float*)Cv  + bb * sCb + hh * sCh;
    __half* Ch = (__half*)Cv + bb * sCb + hh * sCh;
    if (MODE == 2 || MODE == 3) rowsum += (long)bz * TT;

    const int tid  = threadIdx.x;
    const int warp = tid >> 5, lane = tid & 31;
    const int g    = lane >> 2, tig = lane & 3;
    const int r8   = lane & 7, j = lane >> 3;      // LDSM lane roles
    const int wm   = (warp >> 1) * 64;
    const int wn   = (warp & 1)  * 64;
    const int row0 = blockIdx.y * 128;
    const int col0 = blockIdx.x * 128;

    // LDSM lane addressing: rowbase + ((csel | kf*32) ^ xm), xm = (row&7)<<4
    uint32_t arow[4], axm[4];           // A: row = wm + mi*16 + (j&1)*8 + r8
    const uint32_t acsel = (uint32_t)(j >> 1) << 4;
    #pragma unroll
    for (int mi = 0; mi < 4; mi++) {
        int r = wm + mi * 16 + (j & 1) * 8 + r8;
        arow[mi] = (uint32_t)r << 7;
        axm[mi]  = (uint32_t)(r & 7) << 4;
    }
    uint32_t brow[4], bxm[4];           // B: row = wn + p*16 + (j>>1)*8 + r8
    const uint32_t bcsel = (uint32_t)(j & 1) << 4;
    #pragma unroll
    for (int p = 0; p < 4; p++) {
        int r = wn + p * 16 + (j >> 1) * 8 + r8;
        brow[p] = (uint32_t)r << 7;
        bxm[p]  = (uint32_t)(r & 7) << 4;
    }

    float acc[4][8][4] = {};  // [mi][ni][reg]

    // Loader: 128 rows x 64 halfs per operand; 8 x 16B chunks per row.
    const int l_rr = tid >> 3;                    // +p*16 rows per pass
    const uint32_t l_cb = (uint32_t)(tid & 7) << 4;

    #define LOAD_TILE(KT, ST)                                                         \
    {                                                                                 \
        const int _k0 = (KT) * BKH;                                                   \
        const uint32_t _sa = smem_u + (ST) * STAGE_BYTES;                             \
        const uint32_t _sb = smem_u + (NSTAGE + (ST)) * STAGE_BYTES;                  \
        _Pragma("unroll")                                                             \
        for (int p = 0; p < 8; p++) {                                                 \
            int rr = l_rr + p * 16;                                                   \
            uint32_t off = ((uint32_t)rr << 7) + (l_cb ^ ((uint32_t)(rr & 7) << 4));  \
            cp_async16(_sa + off, &A[(size_t)(row0 + rr) * lda + _k0 + (l_cb >> 1)]); \
        }                                                                             \
        _Pragma("unroll")                                                             \
        for (int p = 0; p < 8; p++) {                                                 \
            int rr = l_rr + p * 16;                                                   \
            uint32_t off = ((uint32_t)rr << 7) + (l_cb ^ ((uint32_t)(rr & 7) << 4));  \
            cp_async16(_sb + off, &B[(size_t)(col0 + rr) * ldb + _k0 + (l_cb >> 1)]); \
        }                                                                             \
        cp_commit();                                                                  \
    }

    const int nt = K / BKH;
    LOAD_TILE(0, 0);
    if (nt > 1) LOAD_TILE(1, 1);

    int st = 0;
    for (int kt = 0; kt < nt; kt++) {
        if (kt + 1 < nt) cp_wait<1>(); else cp_wait<0>();
        __syncthreads();

        if (kt + 2 < nt) {
            int st2 = st + 2; if (st2 >= NSTAGE) st2 -= NSTAGE;
            LOAD_TILE(kt + 2, st2);
        }

        const uint32_t as_u = smem_u + st * STAGE_BYTES;
        const uint32_t bs_u = smem_u + (NSTAGE + st) * STAGE_BYTES;

        #pragma unroll
        for (int kf = 0; kf < 4; kf++) {          // 4 x k16 steps (32B each)
            uint32_t af[4][4];
            #pragma unroll
            for (int mi = 0; mi < 4; mi++)
                ldsm_x4(af[mi], as_u + arow[mi] + ((acsel + (kf << 5)) ^ axm[mi]));
            uint32_t bf[4][4];
            #pragma unroll
            for (int p = 0; p < 4; p++)
                ldsm_x4(bf[p], bs_u + brow[p] + ((bcsel + (kf << 5)) ^ bxm[p]));

            #pragma unroll
            for (int mi = 0; mi < 4; mi++)
                #pragma unroll
                for (int ni = 0; ni < 8; ni++) {
                    const uint32_t b0 = bf[ni >> 1][(ni & 1) * 2 + 0];
                    const uint32_t b1 = bf[ni >> 1][(ni & 1) * 2 + 1];
                    asm volatile(
                        "mma.sync.aligned.m16n8k16.row.col.f32.f16.f16.f32 "
                        "{%0,%1,%2,%3},{%4,%5,%6,%7},{%8,%9},{%0,%1,%2,%3};"
                        : "+f"(acc[mi][ni][0]), "+f"(acc[mi][ni][1]),
                          "+f"(acc[mi][ni][2]), "+f"(acc[mi][ni][3])
                        : "r"(af[mi][0]), "r"(af[mi][1]), "r"(af[mi][2]), "r"(af[mi][3]),
                          "r"(b0), "r"(b1));
                }
        }
        st++; if (st >= NSTAGE) st = 0;
    }

    // Epilogue
    #pragma unroll
    for (int mi = 0; mi < 4; mi++) {
        const int r = row0 + wm + mi * 16 + g;

        float inv0 = 1.f, inv1 = 1.f;
        if (MODE == 3) {
            inv0 = 1.0f / rowsum[r];
            inv1 = 1.0f / rowsum[r + 8];
        }
        float s0 = 0.f, s1 = 0.f;

        #pragma unroll
        for (int ni = 0; ni < 8; ni++) {
            const int c = col0 + wn + ni * 8 + tig * 2;
            float v0x = acc[mi][ni][0], v0y = acc[mi][ni][1];
            float v1x = acc[mi][ni][2], v1y = acc[mi][ni][3];

            if (MODE == 2) {
                v0x = exp2f(alpha * v0x); v0y = exp2f(alpha * v0y);
                v1x = exp2f(alpha * v1x); v1y = exp2f(alpha * v1y);
                s0 += v0x + v0y; s1 += v1x + v1y;
            } else if (MODE == 3) {
                v0x *= inv0; v0y *= inv0; v1x *= inv1; v1y *= inv1;
            } else {
                v0x *= alpha; v0y *= alpha; v1x *= alpha; v1y *= alpha;
            }
            if (MODE == 1) {
                *reinterpret_cast<float2*>(&Cf[(size_t)r * ldc + c]) = make_float2(v0x, v0y);
                *reinterpret_cast<float2*>(&Cf[(size_t)(r + 8) * ldc + c]) = make_float2(v1x, v1y);
            } else {
                *reinterpret_cast<__half2*>(&Ch[(size_t)r * ldc + c]) =
                    __floats2half2_rn(v0x, v0y);
                *reinterpret_cast<__half2*>(&Ch[(size_t)(r + 8) * ldc + c]) =
                    __floats2half2_rn(v1x, v1y);
            }
        }

        if (MODE == 2) {
            s0 += __shfl_xor_sync(0xffffffffu, s0, 1);
            s0 += __shfl_xor_sync(0xffffffffu, s0, 2);
            s1 += __shfl_xor_sync(0xffffffffu, s1, 1);
            s1 += __shfl_xor_sync(0xffffffffu, s1, 2);
            if (tig == 0) {
                atomicAdd(&rowsum[r], s0);
                atomicAdd(&rowsum[r + 8], s1);
            }
        }
    }
    #undef LOAD_TILE
}

// ---------------------------------------------------------------------------
// Batched float->half transpose of the three QKV weights.
// ---------------------------------------------------------------------------
__global__ __launch_bounds__(256)
void transpose_f2h3(const float* __restrict__ s0, const float* __restrict__ s1,
                    const float* __restrict__ s2, __half* __restrict__ dst,
                    int lds, int ldd, long dstride)
{
    __shared__ float t[32][33];
    const int z = blockIdx.z;
    const float* src = (z == 0) ? s0 : (z == 1) ? s1 : s2;
    dst += (long)z * dstride;

    const int bx = blockIdx.x * 32;
    const int by = blockIdx.y * 32;
    const int tx = threadIdx.x & 31;
    const int ty = threadIdx.x >> 5;

    #pragma unroll
    for (int jj = 0; jj < 4; jj++)
        t[ty + 8 * jj][tx] = src[(size_t)(by + ty + 8 * jj) * lds + bx + tx];
    __syncthreads();
    #pragma unroll
    for (int jj = 0; jj < 4; jj++)
        dst[(size_t)(bx + ty + 8 * jj) * ldd + by + tx] = __float2half_rn(t[tx][ty + 8 * jj]);
}

__global__ __launch_bounds__(256)
void transpose_f2h(const float* __restrict__ src, __half* __restrict__ dst,
                   int lds, int ldd)
{
    __shared__ float t[32][33];
    const int bx = blockIdx.x * 32;
    const int by = blockIdx.y * 32;
    const int tx = threadIdx.x & 31;
    const int ty = threadIdx.x >> 5;

    #pragma unroll
    for (int jj = 0; jj < 4; jj++)
        t[ty + 8 * jj][tx] = src[(size_t)(by + ty + 8 * jj) * lds + bx + tx];
    __syncthreads();
    #pragma unroll
    for (int jj = 0; jj < 4; jj++)
        dst[(size_t)(bx + ty + 8 * jj) * ldd + by + tx] = __float2half_rn(t[tx][ty + 8 * jj]);
}

// half->half transpose, batched (for v -> vt)
__global__ __launch_bounds__(256)
void transpose_h2h(const __half* __restrict__ src, __half* __restrict__ dst,
                   int lds, int ldd,
                   int nh, long sSb, long sSh, long sDb, long sDh)
{
    __shared__ __half t[32][34];
    const int bz = blockIdx.z;
    const int bb = bz / nh;
    const int hh = bz - bb * nh;
    src += (long)bb * sSb + (long)hh * sSh;
    dst += (long)bb * sDb + (long)hh * sDh;

    const int bx = blockIdx.x * 32;
    const int by = blockIdx.y * 32;
    const int tx = threadIdx.x & 31;
    const int ty = threadIdx.x >> 5;

    #pragma unroll
    for (int jj = 0; jj < 4; jj++)
        t[ty + 8 * jj][tx] = src[(size_t)(by + ty + 8 * jj) * lds + bx + tx];
    __syncthreads();
    #pragma unroll
    for (int jj = 0; jj < 4; jj++)
        dst[(size_t)(bx + ty + 8 * jj) * ldd + by + tx] = t[tx][ty + 8 * jj];
}

// Elementwise float -> half
__global__ __launch_bounds__(256)
void f2h_kernel(const float* __restrict__ src, __half* __restrict__ dst, int n4)
{
    int i = blockIdx.x * 256 + threadIdx.x;
    if (i < n4) {
        float4 v = reinterpret_cast<const float4*>(src)[i];
        reinterpret_cast<__half2*>(dst)[2 * i]     = __floats2half2_rn(v.x, v.y);
        reinterpret_cast<__half2*>(dst)[2 * i + 1] = __floats2half2_rn(v.z, v.w);
    }
}

// Zero rowsum
__global__ __launch_bounds__(256)
void zero_kernel(float* __restrict__ p, int n)
{
    int i = blockIdx.x * 256 + threadIdx.x;
    if (i < n) p[i] = 0.f;
}

// Split-K reduce: out = sum_s psum[s] + bias
__global__ __launch_bounds__(256)
void reduce_kernel(const float* __restrict__ psum, const float* __restrict__ bias,
                   float* __restrict__ out, int n4)
{
    int i = blockIdx.x * 256 + threadIdx.x;
    if (i >= n4) return;
    const int col = (i * 4) % EE;
    float4 b4 = *reinterpret_cast<const float4*>(&bias[col]);
    float4 a = reinterpret_cast<const float4*>(psum)[i];
    float4 b = reinterpret_cast<const float4*>(psum + (size_t)MR * EE)[i];
    float4 c = reinterpret_cast<const float4*>(psum + (size_t)2 * MR * EE)[i];
    float4 o;
    o.x = a.x + b.x + c.x + b4.x;
    o.y = a.y + b.y + c.y + b4.y;
    o.z = a.z + b.z + c.z + b4.z;
    o.w = a.w + b.w + c.w + b4.w;
    reinterpret_cast<float4*>(out)[i] = o;
}

// ---------------------------------------------------------------------------
extern "C" void kernel_launch(void* const* d_in, const int* in_sizes, int n_in,
                              void* d_out, int out_size)
{
    const float* x  = (const float*)d_in[0];   // [4,2048,768]
    const float* Wq = (const float*)d_in[1];   // [768,6144]
    const float* Wk = (const float*)d_in[2];
    const float* Wv = (const float*)d_in[3];
    const float* Wu = (const float*)d_in[4];   // [6144,768]
    const float* bu = (const float*)d_in[5];   // [768]
    float* out = (float*)d_out;                // [8192,768]

    __half *x16, *w16, *qkv, *p16, *vt, *ho;
    float *rowsum, *psum;
    cudaGetSymbolAddress((void**)&x16,    g_x16);
    cudaGetSymbolAddress((void**)&w16,    g_w16);
    cudaGetSymbolAddress((void**)&qkv,    g_qkv);
    cudaGetSymbolAddress((void**)&p16,    g_p16);
    cudaGetSymbolAddress((void**)&rowsum, g_rowsum);
    cudaGetSymbolAddress((void**)&vt,     g_vt);
    cudaGetSymbolAddress((void**)&ho,     g_ho);
    cudaGetSymbolAddress((void**)&psum,   g_psum);

    __half* q = qkv;
    __half* k = qkv + (size_t)MR * HE;
    __half* v = qkv + (size_t)2 * MR * HE;
    const long WSZ = (long)HE * EE;

    cudaFuncSetAttribute(hgemm<0>, cudaFuncAttributeMaxDynamicSharedMemorySize, SMEM_TOTAL);
    cudaFuncSetAttribute(hgemm<1>, cudaFuncAttributeMaxDynamicSharedMemorySize, SMEM_TOTAL);
    cudaFuncSetAttribute(hgemm<2>, cudaFuncAttributeMaxDynamicSharedMemorySize, SMEM_TOTAL);
    cudaFuncSetAttribute(hgemm<3>, cudaFuncAttributeMaxDynamicSharedMemorySize, SMEM_TOTAL);

    const dim3 blk(256);
    const dim3 gblk(128);
    const float alpha_exp = 1.4426950408889634f / sqrtf((float)EE);

    // Launch order puts the scores hgemm at index 5 (ncu -s 5 samples it).
    zero_kernel<<<(BB * HH * TT + 255) / 256, blk>>>(rowsum, BB * HH * TT);           // 0
    f2h_kernel<<<(MR * EE / 4 + 255) / 256, blk>>>(x, x16, MR * EE / 4);              // 1
    transpose_f2h3<<<dim3(HE/32, EE/32, 3), blk>>>(Wq, Wk, Wv, w16, HE, EE, WSZ);     // 2
    transpose_f2h<<<dim3(EE/32, HE/32, 1), blk>>>(Wu, w16 + 3*WSZ, EE, HE);           // 3

    // 4: QKV projections (batched z=3)
    hgemm<0><<<dim3(HE/128, MR/128, 3), gblk, SMEM_TOTAL>>>(
        x16, w16, qkv, nullptr,
        EE, EE, EE, HE,
        1, 0, 0, WSZ, 0, (long)MR * HE, 0, 1.f);

    // 5: scores + exp + rowsum  (ncu-sampled)
    hgemm<2><<<dim3(TT/128, TT/128, BB*HH), gblk, SMEM_TOTAL>>>(
        q, k, p16, rowsum,
        EE, HE, HE, TT,
        HH, (long)TT * HE, (long)EE, (long)TT * HE, (long)EE,
        (long)HH * TT * TT, (long)TT * TT, alpha_exp);

    // 6: transpose v -> vt [b,h,e,t]
    transpose_h2h<<<dim3(EE/32, TT/32, BB*HH), blk>>>(
        v, vt, HE, TT,
        HH, (long)TT * HE, (long)EE, (long)HH * EE * TT, (long)EE * TT);

    // 7: O = (p @ v) / rowsum -> ho fp16
    hgemm<3><<<dim3(EE/128, TT/128, BB*HH), gblk, SMEM_TOTAL>>>(
        p16, vt, ho, rowsum,
        TT, TT, TT, HE,
        HH, (long)HH * TT * TT, (long)TT * TT,
        (long)HH * EE * TT, (long)EE * TT,
        (long)TT * HE, (long)EE, 1.f);

    // 8: output projection, split-K=3 into psum (z = split)
    hgemm<1><<<dim3(EE/128, MR/128, NSPLIT), gblk, SMEM_TOTAL>>>(
        ho, w16 + 3*WSZ, psum, nullptr,
        HE / NSPLIT, HE, HE, EE,
        1, (long)(HE / NSPLIT), 0, (long)(HE / NSPLIT), 0,
        (long)MR * EE, 0, 1.f);

    // 9: reduce partials + bias -> fp32 out
    reduce_kernel<<<(MR * EE / 4 + 255) / 256, blk>>>(psum, bu, out, MR * EE / 4);
}

// round 11
// speedup vs baseline: 9.6482x; 1.0332x over previous
#include <cuda_runtime.h>
#include <cuda_fp16.h>
#include <math.h>
#include <stdint.h>

// Problem shape (fixed by the reference)
#define BB 4
#define TT 2048
#define EE 768
#define HH 8
#define HE 6144          // H*E
#define MR 8192          // B*T
#define NSPLIT 3         // split-K for final projection

// Scratch (allocation-free rule -> __device__ globals)
__device__ __half g_x16[(size_t)MR * EE];                 // x in fp16
__device__ __half g_w16[(size_t)4 * HE * EE];             // Wq|Wk|Wv|Wu fp16 (native layout)
__device__ __half g_qkv[(size_t)3 * MR * HE];             // q|k|v fp16
__device__ __half g_p16[(size_t)BB * HH * (size_t)TT * TT]; // unnormalized exp(logit)
__device__ float  g_rowsum[(size_t)BB * HH * TT];         // per-row sum of exp
__device__ __half g_ho[(size_t)MR * HE];                  // attention out fp16
__device__ float  g_psum[(size_t)NSPLIT * MR * EE];       // split-K partials

// Tiling: CTA 128x128, BK=64 halfs, 3-stage cp.async ring, XOR swizzle.
#define BKH 64
#define STAGE_BYTES 16384               // one operand tile (both layouts): 16 KB
#define NSTAGE 3
#define SMEM_TOTAL (2 * NSTAGE * STAGE_BYTES)   // 98304 B

__device__ __forceinline__ void cp_async16(uint32_t smem_dst, const void* gmem_src) {
    asm volatile("cp.async.cg.shared.global [%0], [%1], 16;" :: "r"(smem_dst), "l"(gmem_src));
}
__device__ __forceinline__ void cp_commit() { asm volatile("cp.async.commit_group;" ::: "memory"); }
template<int N>
__device__ __forceinline__ void cp_wait() { asm volatile("cp.async.wait_group %0;" :: "n"(N) : "memory"); }
__device__ __forceinline__ void ldsm_x4(uint32_t (&d)[4], uint32_t addr) {
    asm volatile("ldmatrix.sync.aligned.m8n8.x4.shared.b16 {%0,%1,%2,%3}, [%4];"
        : "=r"(d[0]), "=r"(d[1]), "=r"(d[2]), "=r"(d[3]) : "r"(addr));
}
__device__ __forceinline__ void ldsm_x4_t(uint32_t (&d)[4], uint32_t addr) {
    asm volatile("ldmatrix.sync.aligned.m8n8.x4.trans.shared.b16 {%0,%1,%2,%3}, [%4];"
        : "=r"(d[0]), "=r"(d[1]), "=r"(d[2]), "=r"(d[3]) : "r"(addr));
}

// ---------------------------------------------------------------------------
// fp16 tensor-core GEMM (m16n8k16). C = alpha * A[M,K] @ B (+epilogue).
// TRANSB=false: B is K-major [N,K] rows (scores: B=k).
// TRANSB=true:  B is N-major [K,N] rows (W, v) -> ldmatrix.trans.
// MODE: 0 = fp16 out (alpha), 1 = fp32 out (alpha), 2 = EXPSUM, 3 = NORM.
// 4 warps, warp tile 64x64, 3-stage cp.async ring.
// ---------------------------------------------------------------------------
template<int MODE, bool TRANSB>
__global__ __launch_bounds__(128, 2)
void hgemm(const __half* __restrict__ A, const __half* __restrict__ B,
           void* __restrict__ Cv, float* __restrict__ rowsum,
           int K, int lda, int ldb, int ldc,
           int nh, long sAb, long sAh, long sBb, long sBh,
           long sCb, long sCh, float alpha)
{
    extern __shared__ __half smem[];
    const uint32_t smem_u = (uint32_t)__cvta_generic_to_shared(smem);

    const int bz = blockIdx.z;
    const int bb = bz / nh;
    const int hh = bz - bb * nh;
    A += (long)bb * sAb + (long)hh * sAh;
    B += (long)bb * sBb + (long)hh * sBh;
    float*  Cf = (float*)Cv  + bb * sCb + hh * sCh;
    __half* Ch = (__half*)Cv + bb * sCb + hh * sCh;
    if (MODE == 2 || MODE == 3) rowsum += (long)bz * TT;

    const int tid  = threadIdx.x;
    const int warp = tid >> 5, lane = tid & 31;
    const int g    = lane >> 2, tig = lane & 3;
    const int r8   = lane & 7, j = lane >> 3;      // LDSM lane roles
    const int wm   = (warp >> 1) * 64;
    const int wn   = (warp & 1)  * 64;
    const int row0 = blockIdx.y * 128;
    const int col0 = blockIdx.x * 128;

    // A fragments (K-major, 128B rows): rowbase + ((csel + kf*32) ^ xm)
    uint32_t arow[4], axm[4];
    const uint32_t acsel = (uint32_t)(j >> 1) << 4;
    #pragma unroll
    for (int mi = 0; mi < 4; mi++) {
        int r = wm + mi * 16 + (j & 1) * 8 + r8;
        arow[mi] = (uint32_t)r << 7;
        axm[mi]  = (uint32_t)(r & 7) << 4;
    }
    // B fragments
    uint32_t brow[4], bxm[4];            // non-trans (K-major 128B rows)
    uint32_t btb[4];                     // trans (N-major 256B rows)
    const uint32_t bcsel = (uint32_t)(j & 1) << 4;
    if (!TRANSB) {
        #pragma unroll
        for (int p = 0; p < 4; p++) {
            int r = wn + p * 16 + (j >> 1) * 8 + r8;
            brow[p] = (uint32_t)r << 7;
            bxm[p]  = (uint32_t)(r & 7) << 4;
        }
    } else {
        // block j: row = (j&1)*8 + r8 (k-oct), col = wn*2 + p*32 + (j>>1)*16 (n-oct)
        // swizzle XOR applied to the FULL 16B-aligned column offset (stays < 256)
        const uint32_t xtm = (uint32_t)r8 << 4;
        #pragma unroll
        for (int p = 0; p < 4; p++)
            btb[p] = (uint32_t)((j & 1) * 8 + r8) * 256
                   + (((uint32_t)(wn * 2 + p * 32 + (j >> 1) * 16)) ^ xtm);
    }

    float acc[4][8][4] = {};  // [mi][ni][reg]

    // Loaders. A: 128 rows x 128B. B non-trans: same. B trans: 64 rows x 256B.
    const int a_rr = tid >> 3;                       // +p*16
    const uint32_t a_cb = (uint32_t)(tid & 7) << 4;
    const int t_rr = tid >> 4;                       // +p*8 (trans tile)
    const uint32_t t_c16 = (uint32_t)(tid & 15) << 4;

    #define LOAD_TILE(KT, ST)                                                         \
    {                                                                                 \
        const int _k0 = (KT) * BKH;                                                   \
        const uint32_t _sa = smem_u + (ST) * STAGE_BYTES;                             \
        const uint32_t _sb = smem_u + (NSTAGE + (ST)) * STAGE_BYTES;                  \
        _Pragma("unroll")                                                             \
        for (int p = 0; p < 8; p++) {                                                 \
            int rr = a_rr + p * 16;                                                   \
            uint32_t off = ((uint32_t)rr << 7) + (a_cb ^ ((uint32_t)(rr & 7) << 4));  \
            cp_async16(_sa + off, &A[(size_t)(row0 + rr) * lda + _k0 + (a_cb >> 1)]); \
        }                                                                             \
        if (TRANSB) {                                                                 \
            _Pragma("unroll")                                                         \
            for (int p = 0; p < 8; p++) {                                             \
                int rr = t_rr + p * 8;                                                \
                uint32_t off = ((uint32_t)rr << 8) + (t_c16 ^ ((uint32_t)(rr & 7) << 4)); \
                cp_async16(_sb + off, &B[(size_t)(_k0 + rr) * ldb + col0 + (t_c16 >> 1)]); \
            }                                                                         \
        } else {                                                                      \
            _Pragma("unroll")                                                         \
            for (int p = 0; p < 8; p++) {                                             \
                int rr = a_rr + p * 16;                                               \
                uint32_t off = ((uint32_t)rr << 7) + (a_cb ^ ((uint32_t)(rr & 7) << 4)); \
                cp_async16(_sb + off, &B[(size_t)(col0 + rr) * ldb + _k0 + (a_cb >> 1)]); \
            }                                                                         \
        }                                                                             \
        cp_commit();                                                                  \
    }

    const int nt = K / BKH;
    LOAD_TILE(0, 0);
    if (nt > 1) LOAD_TILE(1, 1);

    int st = 0;
    for (int kt = 0; kt < nt; kt++) {
        if (kt + 1 < nt) cp_wait<1>(); else cp_wait<0>();
        __syncthreads();

        if (kt + 2 < nt) {
            int st2 = st + 2; if (st2 >= NSTAGE) st2 -= NSTAGE;
            LOAD_TILE(kt + 2, st2);
        }

        const uint32_t as_u = smem_u + st * STAGE_BYTES;
        const uint32_t bs_u = smem_u + (NSTAGE + st) * STAGE_BYTES;

        #pragma unroll
        for (int kf = 0; kf < 4; kf++) {          // 4 x k16 steps
            uint32_t af[4][4];
            #pragma unroll
            for (int mi = 0; mi < 4; mi++)
                ldsm_x4(af[mi], as_u + arow[mi] + ((acsel + (kf << 5)) ^ axm[mi]));
            uint32_t bf[4][4];
            if (TRANSB) {
                // kf advances 16 k-rows = 16*256 B; (row&7) unchanged
                #pragma unroll
                for (int p = 0; p < 4; p++)
                    ldsm_x4_t(bf[p], bs_u + btb[p] + ((uint32_t)kf << 12));
            } else {
                #pragma unroll
                for (int p = 0; p < 4; p++)
                    ldsm_x4(bf[p], bs_u + brow[p] + ((bcsel + (kf << 5)) ^ bxm[p]));
            }

            #pragma unroll
            for (int mi = 0; mi < 4; mi++)
                #pragma unroll
                for (int ni = 0; ni < 8; ni++) {
                    const uint32_t b0 = bf[ni >> 1][(ni & 1) * 2 + 0];
                    const uint32_t b1 = bf[ni >> 1][(ni & 1) * 2 + 1];
                    asm volatile(
                        "mma.sync.aligned.m16n8k16.row.col.f32.f16.f16.f32 "
                        "{%0,%1,%2,%3},{%4,%5,%6,%7},{%8,%9},{%0,%1,%2,%3};"
                        : "+f"(acc[mi][ni][0]), "+f"(acc[mi][ni][1]),
                          "+f"(acc[mi][ni][2]), "+f"(acc[mi][ni][3])
                        : "r"(af[mi][0]), "r"(af[mi][1]), "r"(af[mi][2]), "r"(af[mi][3]),
                          "r"(b0), "r"(b1));
                }
        }
        st++; if (st >= NSTAGE) st = 0;
    }

    // Epilogue
    #pragma unroll
    for (int mi = 0; mi < 4; mi++) {
        const int r = row0 + wm + mi * 16 + g;

        float inv0 = 1.f, inv1 = 1.f;
        if (MODE == 3) {
            inv0 = 1.0f / rowsum[r];
            inv1 = 1.0f / rowsum[r + 8];
        }
        float s0 = 0.f, s1 = 0.f;

        #pragma unroll
        for (int ni = 0; ni < 8; ni++) {
            const int c = col0 + wn + ni * 8 + tig * 2;
            float v0x = acc[mi][ni][0], v0y = acc[mi][ni][1];
            float v1x = acc[mi][ni][2], v1y = acc[mi][ni][3];

            if (MODE == 2) {
                v0x = exp2f(alpha * v0x); v0y = exp2f(alpha * v0y);
                v1x = exp2f(alpha * v1x); v1y = exp2f(alpha * v1y);
                s0 += v0x + v0y; s1 += v1x + v1y;
            } else if (MODE == 3) {
                v0x *= inv0; v0y *= inv0; v1x *= inv1; v1y *= inv1;
            } else {
                v0x *= alpha; v0y *= alpha; v1x *= alpha; v1y *= alpha;
            }
            if (MODE == 1) {
                *reinterpret_cast<float2*>(&Cf[(size_t)r * ldc + c]) = make_float2(v0x, v0y);
                *reinterpret_cast<float2*>(&Cf[(size_t)(r + 8) * ldc + c]) = make_float2(v1x, v1y);
            } else {
                *reinterpret_cast<__half2*>(&Ch[(size_t)r * ldc + c]) =
                    __floats2half2_rn(v0x, v0y);
                *reinterpret_cast<__half2*>(&Ch[(size_t)(r + 8) * ldc + c]) =
                    __floats2half2_rn(v1x, v1y);
            }
        }

        if (MODE == 2) {
            s0 += __shfl_xor_sync(0xffffffffu, s0, 1);
            s0 += __shfl_xor_sync(0xffffffffu, s0, 2);
            s1 += __shfl_xor_sync(0xffffffffu, s1, 1);
            s1 += __shfl_xor_sync(0xffffffffu, s1, 2);
            if (tig == 0) {
                atomicAdd(&rowsum[r], s0);
                atomicAdd(&rowsum[r + 8], s1);
            }
        }
    }
    #undef LOAD_TILE
}

// Elementwise float -> half
__global__ __launch_bounds__(256)
void f2h_kernel(const float* __restrict__ src, __half* __restrict__ dst, int n4)
{
    int i = blockIdx.x * 256 + threadIdx.x;
    if (i < n4) {
        float4 v = reinterpret_cast<const float4*>(src)[i];
        reinterpret_cast<__half2*>(dst)[2 * i]     = __floats2half2_rn(v.x, v.y);
        reinterpret_cast<__half2*>(dst)[2 * i + 1] = __floats2half2_rn(v.z, v.w);
    }
}

// Batched f2h over the four weight matrices (all 768*6144 = 4.7M elements)
__global__ __launch_bounds__(256)
void f2h_w4(const float* __restrict__ s0, const float* __restrict__ s1,
            const float* __restrict__ s2, const float* __restrict__ s3,
            __half* __restrict__ dst, int n4, long dstride)
{
    const int z = blockIdx.z;
    const float* src = (z == 0) ? s0 : (z == 1) ? s1 : (z == 2) ? s2 : s3;
    dst += (long)z * dstride;
    int i = blockIdx.x * 256 + threadIdx.x;
    if (i < n4) {
        float4 v = reinterpret_cast<const float4*>(src)[i];
        reinterpret_cast<__half2*>(dst)[2 * i]     = __floats2half2_rn(v.x, v.y);
        reinterpret_cast<__half2*>(dst)[2 * i + 1] = __floats2half2_rn(v.z, v.w);
    }
}

// Zero rowsum
__global__ __launch_bounds__(256)
void zero_kernel(float* __restrict__ p, int n)
{
    int i = blockIdx.x * 256 + threadIdx.x;
    if (i < n) p[i] = 0.f;
}

// Split-K reduce: out = sum_s psum[s] + bias
__global__ __launch_bounds__(256)
void reduce_kernel(const float* __restrict__ psum, const float* __restrict__ bias,
                   float* __restrict__ out, int n4)
{
    int i = blockIdx.x * 256 + threadIdx.x;
    if (i >= n4) return;
    const int col = (i * 4) % EE;
    float4 b4 = *reinterpret_cast<const float4*>(&bias[col]);
    float4 a = reinterpret_cast<const float4*>(psum)[i];
    float4 b = reinterpret_cast<const float4*>(psum + (size_t)MR * EE)[i];
    float4 c = reinterpret_cast<const float4*>(psum + (size_t)2 * MR * EE)[i];
    float4 o;
    o.x = a.x + b.x + c.x + b4.x;
    o.y = a.y + b.y + c.y + b4.y;
    o.z = a.z + b.z + c.z + b4.z;
    o.w = a.w + b.w + c.w + b4.w;
    reinterpret_cast<float4*>(out)[i] = o;
}

// ---------------------------------------------------------------------------
extern "C" void kernel_launch(void* const* d_in, const int* in_sizes, int n_in,
                              void* d_out, int out_size)
{
    const float* x  = (const float*)d_in[0];   // [4,2048,768]
    const float* Wq = (const float*)d_in[1];   // [768,6144]
    const float* Wk = (const float*)d_in[2];
    const float* Wv = (const float*)d_in[3];
    const float* Wu = (const float*)d_in[4];   // [6144,768]
    const float* bu = (const float*)d_in[5];   // [768]
    float* out = (float*)d_out;                // [8192,768]

    __half *x16, *w16, *qkv, *p16, *ho;
    float *rowsum, *psum;
    cudaGetSymbolAddress((void**)&x16,    g_x16);
    cudaGetSymbolAddress((void**)&w16,    g_w16);
    cudaGetSymbolAddress((void**)&qkv,    g_qkv);
    cudaGetSymbolAddress((void**)&p16,    g_p16);
    cudaGetSymbolAddress((void**)&rowsum, g_rowsum);
    cudaGetSymbolAddress((void**)&ho,     g_ho);
    cudaGetSymbolAddress((void**)&psum,   g_psum);

    __half* q = qkv;
    __half* k = qkv + (size_t)MR * HE;
    __half* v = qkv + (size_t)2 * MR * HE;
    const long WSZ = (long)HE * EE;
    __half* w16u = w16 + 3 * WSZ;              // Wu fp16, native [6144,768]

    cudaFuncSetAttribute(hgemm<0, true >, cudaFuncAttributeMaxDynamicSharedMemorySize, SMEM_TOTAL);
    cudaFuncSetAttribute(hgemm<1, true >, cudaFuncAttributeMaxDynamicSharedMemorySize, SMEM_TOTAL);
    cudaFuncSetAttribute(hgemm<2, false>, cudaFuncAttributeMaxDynamicSharedMemorySize, SMEM_TOTAL);
    cudaFuncSetAttribute(hgemm<3, true >, cudaFuncAttributeMaxDynamicSharedMemorySize, SMEM_TOTAL);

    const dim3 blk(256);
    const dim3 gblk(128);
    const float alpha_exp = 1.4426950408889634f / sqrtf((float)EE);
    const int WN4 = (int)(WSZ / 4);

    // 0: zero rowsum; 1: x -> fp16; 2: weights -> fp16 (native layout, z=4)
    zero_kernel<<<(BB * HH * TT + 255) / 256, blk>>>(rowsum, BB * HH * TT);
    f2h_kernel<<<(MR * EE / 4 + 255) / 256, blk>>>(x, x16, MR * EE / 4);
    f2h_w4<<<dim3((WN4 + 255) / 256, 1, 4), blk>>>(Wq, Wk, Wv, Wu, w16, WN4, WSZ);

    // 3: QKV projections (batched z=3), B = W (N-major, trans-load)
    hgemm<0, true><<<dim3(HE/128, MR/128, 3), gblk, SMEM_TOTAL>>>(
        x16, w16, qkv, nullptr,
        EE, EE, HE, HE,
        1, 0, 0, WSZ, 0, (long)MR * HE, 0, 1.f);

    // 4: scores + exp + rowsum (B = k, K-major)
    hgemm<2, false><<<dim3(TT/128, TT/128, BB*HH), gblk, SMEM_TOTAL>>>(
        q, k, p16, rowsum,
        EE, HE, HE, TT,
        HH, (long)TT * HE, (long)EE, (long)TT * HE, (long)EE,
        (long)HH * TT * TT, (long)TT * TT, alpha_exp);

    // 5: O = (p @ v) / rowsum -> ho fp16  (B = v, N-major trans-load)
    hgemm<3, true><<<dim3(EE/128, TT/128, BB*HH), gblk, SMEM_TOTAL>>>(
        p16, v, ho, rowsum,
        TT, TT, HE, HE,
        HH, (long)HH * TT * TT, (long)TT * TT,
        (long)TT * HE, (long)EE,
        (long)TT * HE, (long)EE, 1.f);

    // 6: output projection, split-K=3 (B = Wu, N-major trans-load)
    hgemm<1, true><<<dim3(EE/128, MR/128, NSPLIT), gblk, SMEM_TOTAL>>>(
        ho, w16u, psum, nullptr,
        HE / NSPLIT, HE, EE, EE,
        1, (long)(HE / NSPLIT), 0, (long)(HE / NSPLIT) * EE, 0,
        (long)MR * EE, 0, 1.f);

    // 7: reduce partials + bias -> fp32 out
    reduce_kernel<<<(MR * EE / 4 + 255) / 256, blk>>>(psum, bu, out, MR * EE / 4);
}

// round 12
// speedup vs baseline: 9.6541x; 1.0006x over previous
#include <cuda_runtime.h>
#include <cuda_fp16.h>
#include <math.h>
#include <stdint.h>

// Problem shape (fixed by the reference)
#define BB 4
#define TT 2048
#define EE 768
#define HH 8
#define HE 6144          // H*E
#define MR 8192          // B*T
#define NSPLIT 3         // split-K for final projection

// Scratch (allocation-free rule -> __device__ globals)
__device__ __half g_x16[(size_t)MR * EE];                 // x in fp16
__device__ __half g_w16[(size_t)4 * HE * EE];             // Wq|Wk|Wv|Wu fp16 (native layout)
__device__ __half g_qkv[(size_t)3 * MR * HE];             // q|k|v fp16
__device__ __half g_p16[(size_t)BB * HH * (size_t)TT * TT]; // unnormalized exp(logit)
__device__ float  g_rowsum[(size_t)BB * HH * TT];         // per-row sum of exp
__device__ __half g_ho[(size_t)MR * HE];                  // attention out fp16
__device__ float  g_psum[(size_t)NSPLIT * MR * EE];       // split-K partials

// Tiling: CTA 128x128, BK=64 halfs, 3-stage cp.async ring, XOR swizzle.
#define BKH 64
#define STAGE_BYTES 16384               // one operand tile (both layouts): 16 KB
#define NSTAGE 3
#define SMEM_TOTAL (2 * NSTAGE * STAGE_BYTES)   // 98304 B

__device__ __forceinline__ void cp_async16(uint32_t smem_dst, const void* gmem_src) {
    asm volatile("cp.async.cg.shared.global [%0], [%1], 16;" :: "r"(smem_dst), "l"(gmem_src));
}
__device__ __forceinline__ void cp_commit() { asm volatile("cp.async.commit_group;" ::: "memory"); }
template<int N>
__device__ __forceinline__ void cp_wait() { asm volatile("cp.async.wait_group %0;" :: "n"(N) : "memory"); }
__device__ __forceinline__ void ldsm_x4(uint32_t (&d)[4], uint32_t addr) {
    asm volatile("ldmatrix.sync.aligned.m8n8.x4.shared.b16 {%0,%1,%2,%3}, [%4];"
        : "=r"(d[0]), "=r"(d[1]), "=r"(d[2]), "=r"(d[3]) : "r"(addr));
}
__device__ __forceinline__ void ldsm_x4_t(uint32_t (&d)[4], uint32_t addr) {
    asm volatile("ldmatrix.sync.aligned.m8n8.x4.trans.shared.b16 {%0,%1,%2,%3}, [%4];"
        : "=r"(d[0]), "=r"(d[1]), "=r"(d[2]), "=r"(d[3]) : "r"(addr));
}

// ---------------------------------------------------------------------------
// fp16 tensor-core GEMM (m16n8k16). C = alpha * A[M,K] @ B (+epilogue).
// TRANSB=false: B is K-major [N,K] rows (scores: B=k).
// TRANSB=true:  B is N-major [K,N] rows (W, v) -> ldmatrix.trans.
// MODE: 0 = fp16 out (alpha), 1 = fp32 out (alpha), 2 = EXPSUM, 3 = NORM.
// 4 warps, warp tile 64x64, 3-stage cp.async ring.
// LDSM issue interleaved A/B so first HMMA's operands are oldest loads.
// ---------------------------------------------------------------------------
template<int MODE, bool TRANSB>
__global__ __launch_bounds__(128, 2)
void hgemm(const __half* __restrict__ A, const __half* __restrict__ B,
           void* __restrict__ Cv, float* __restrict__ rowsum,
           int K, int lda, int ldb, int ldc,
           int nh, long sAb, long sAh, long sBb, long sBh,
           long sCb, long sCh, float alpha)
{
    extern __shared__ __half smem[];
    const uint32_t smem_u = (uint32_t)__cvta_generic_to_shared(smem);

    const int bz = blockIdx.z;
    const int bb = bz / nh;
    const int hh = bz - bb * nh;
    A += (long)bb * sAb + (long)hh * sAh;
    B += (long)bb * sBb + (long)hh * sBh;
    float*  Cf = (float*)Cv  + bb * sCb + hh * sCh;
    __half* Ch = (__half*)Cv + bb * sCb + hh * sCh;
    if (MODE == 2 || MODE == 3) rowsum += (long)bz * TT;

    const int tid  = threadIdx.x;
    const int warp = tid >> 5, lane = tid & 31;
    const int g    = lane >> 2, tig = lane & 3;
    const int r8   = lane & 7, j = lane >> 3;      // LDSM lane roles
    const int wm   = (warp >> 1) * 64;
    const int wn   = (warp & 1)  * 64;
    const int row0 = blockIdx.y * 128;
    const int col0 = blockIdx.x * 128;

    // A fragments (K-major, 128B rows): rowbase + ((csel + kf*32) ^ xm)
    uint32_t arow[4], axm[4];
    const uint32_t acsel = (uint32_t)(j >> 1) << 4;
    #pragma unroll
    for (int mi = 0; mi < 4; mi++) {
        int r = wm + mi * 16 + (j & 1) * 8 + r8;
        arow[mi] = (uint32_t)r << 7;
        axm[mi]  = (uint32_t)(r & 7) << 4;
    }
    // B fragments
    uint32_t brow[4], bxm[4];            // non-trans (K-major 128B rows)
    uint32_t btb[4];                     // trans (N-major 256B rows)
    const uint32_t bcsel = (uint32_t)(j & 1) << 4;
    if (!TRANSB) {
        #pragma unroll
        for (int p = 0; p < 4; p++) {
            int r = wn + p * 16 + (j >> 1) * 8 + r8;
            brow[p] = (uint32_t)r << 7;
            bxm[p]  = (uint32_t)(r & 7) << 4;
        }
    } else {
        // block j: row = (j&1)*8 + r8 (k-oct), col = wn*2 + p*32 + (j>>1)*16
        // swizzle XOR applied to the FULL 16B-aligned column offset (< 256)
        const uint32_t xtm = (uint32_t)r8 << 4;
        #pragma unroll
        for (int p = 0; p < 4; p++)
            btb[p] = (uint32_t)((j & 1) * 8 + r8) * 256
                   + (((uint32_t)(wn * 2 + p * 32 + (j >> 1) * 16)) ^ xtm);
    }

    float acc[4][8][4] = {};  // [mi][ni][reg]

    // Loaders. A: 128 rows x 128B. B non-trans: same. B trans: 64 rows x 256B.
    const int a_rr = tid >> 3;                       // +p*16
    const uint32_t a_cb = (uint32_t)(tid & 7) << 4;
    const int t_rr = tid >> 4;                       // +p*8 (trans tile)
    const uint32_t t_c16 = (uint32_t)(tid & 15) << 4;

    #define LOAD_TILE(KT, ST)                                                         \
    {                                                                                 \
        const int _k0 = (KT) * BKH;                                                   \
        const uint32_t _sa = smem_u + (ST) * STAGE_BYTES;                             \
        const uint32_t _sb = smem_u + (NSTAGE + (ST)) * STAGE_BYTES;                  \
        _Pragma("unroll")                                                             \
        for (int p = 0; p < 8; p++) {                                                 \
            int rr = a_rr + p * 16;                                                   \
            uint32_t off = ((uint32_t)rr << 7) + (a_cb ^ ((uint32_t)(rr & 7) << 4));  \
            cp_async16(_sa + off, &A[(size_t)(row0 + rr) * lda + _k0 + (a_cb >> 1)]); \
        }                                                                             \
        if (TRANSB) {                                                                 \
            _Pragma("unroll")                                                         \
            for (int p = 0; p < 8; p++) {                                             \
                int rr = t_rr + p * 8;                                                \
                uint32_t off = ((uint32_t)rr << 8) + (t_c16 ^ ((uint32_t)(rr & 7) << 4)); \
                cp_async16(_sb + off, &B[(size_t)(_k0 + rr) * ldb + col0 + (t_c16 >> 1)]); \
            }                                                                         \
        } else {                                                                      \
            _Pragma("unroll")                                                         \
            for (int p = 0; p < 8; p++) {                                             \
                int rr = a_rr + p * 16;                                               \
                uint32_t off = ((uint32_t)rr << 7) + (a_cb ^ ((uint32_t)(rr & 7) << 4)); \
                cp_async16(_sb + off, &B[(size_t)(col0 + rr) * ldb + _k0 + (a_cb >> 1)]); \
            }                                                                         \
        }                                                                             \
        cp_commit();                                                                  \
    }

    const int nt = K / BKH;
    LOAD_TILE(0, 0);
    if (nt > 1) LOAD_TILE(1, 1);

    int st = 0;
    for (int kt = 0; kt < nt; kt++) {
        if (kt + 1 < nt) cp_wait<1>(); else cp_wait<0>();
        __syncthreads();

        if (kt + 2 < nt) {
            int st2 = st + 2; if (st2 >= NSTAGE) st2 -= NSTAGE;
            LOAD_TILE(kt + 2, st2);
        }

        const uint32_t as_u = smem_u + st * STAGE_BYTES;
        const uint32_t bs_u = smem_u + (NSTAGE + st) * STAGE_BYTES;

        #pragma unroll
        for (int kf = 0; kf < 4; kf++) {          // 4 x k16 steps
            uint32_t af[4][4];
            uint32_t bf[4][4];
            // Interleaved issue: af[p], bf[p] pairs. asm volatile preserves
            // program order, so the first HMMA (af[0], bf[0]) depends on the
            // two OLDEST loads (6 LDSM slots of cover) instead of bf[0]
            // being issued 4 slots before use.
            #pragma unroll
            for (int p = 0; p < 4; p++) {
                ldsm_x4(af[p], as_u + arow[p] + ((acsel + (kf << 5)) ^ axm[p]));
                if (TRANSB) {
                    // kf advances 16 k-rows = 16*256 B; (row&7) unchanged
                    ldsm_x4_t(bf[p], bs_u + btb[p] + ((uint32_t)kf << 12));
                } else {
                    ldsm_x4(bf[p], bs_u + brow[p] + ((bcsel + (kf << 5)) ^ bxm[p]));
                }
            }

            #pragma unroll
            for (int mi = 0; mi < 4; mi++)
                #pragma unroll
                for (int ni = 0; ni < 8; ni++) {
                    const uint32_t b0 = bf[ni >> 1][(ni & 1) * 2 + 0];
                    const uint32_t b1 = bf[ni >> 1][(ni & 1) * 2 + 1];
                    asm volatile(
                        "mma.sync.aligned.m16n8k16.row.col.f32.f16.f16.f32 "
                        "{%0,%1,%2,%3},{%4,%5,%6,%7},{%8,%9},{%0,%1,%2,%3};"
                        : "+f"(acc[mi][ni][0]), "+f"(acc[mi][ni][1]),
                          "+f"(acc[mi][ni][2]), "+f"(acc[mi][ni][3])
                        : "r"(af[mi][0]), "r"(af[mi][1]), "r"(af[mi][2]), "r"(af[mi][3]),
                          "r"(b0), "r"(b1));
                }
        }
        st++; if (st >= NSTAGE) st = 0;
    }

    // Epilogue
    #pragma unroll
    for (int mi = 0; mi < 4; mi++) {
        const int r = row0 + wm + mi * 16 + g;

        float inv0 = 1.f, inv1 = 1.f;
        if (MODE == 3) {
            inv0 = 1.0f / rowsum[r];
            inv1 = 1.0f / rowsum[r + 8];
        }
        float s0 = 0.f, s1 = 0.f;

        #pragma unroll
        for (int ni = 0; ni < 8; ni++) {
            const int c = col0 + wn + ni * 8 + tig * 2;
            float v0x = acc[mi][ni][0], v0y = acc[mi][ni][1];
            float v1x = acc[mi][ni][2], v1y = acc[mi][ni][3];

            if (MODE == 2) {
                v0x = exp2f(alpha * v0x); v0y = exp2f(alpha * v0y);
                v1x = exp2f(alpha * v1x); v1y = exp2f(alpha * v1y);
                s0 += v0x + v0y; s1 += v1x + v1y;
            } else if (MODE == 3) {
                v0x *= inv0; v0y *= inv0; v1x *= inv1; v1y *= inv1;
            } else {
                v0x *= alpha; v0y *= alpha; v1x *= alpha; v1y *= alpha;
            }
            if (MODE == 1) {
                *reinterpret_cast<float2*>(&Cf[(size_t)r * ldc + c]) = make_float2(v0x, v0y);
                *reinterpret_cast<float2*>(&Cf[(size_t)(r + 8) * ldc + c]) = make_float2(v1x, v1y);
            } else {
                *reinterpret_cast<__half2*>(&Ch[(size_t)r * ldc + c]) =
                    __floats2half2_rn(v0x, v0y);
                *reinterpret_cast<__half2*>(&Ch[(size_t)(r + 8) * ldc + c]) =
                    __floats2half2_rn(v1x, v1y);
            }
        }

        if (MODE == 2) {
            s0 += __shfl_xor_sync(0xffffffffu, s0, 1);
            s0 += __shfl_xor_sync(0xffffffffu, s0, 2);
            s1 += __shfl_xor_sync(0xffffffffu, s1, 1);
            s1 += __shfl_xor_sync(0xffffffffu, s1, 2);
            if (tig == 0) {
                atomicAdd(&rowsum[r], s0);
                atomicAdd(&rowsum[r + 8], s1);
            }
        }
    }
    #undef LOAD_TILE
}

// Elementwise float -> half
__global__ __launch_bounds__(256)
void f2h_kernel(const float* __restrict__ src, __half* __restrict__ dst, int n4)
{
    int i = blockIdx.x * 256 + threadIdx.x;
    if (i < n4) {
        float4 v = reinterpret_cast<const float4*>(src)[i];
        reinterpret_cast<__half2*>(dst)[2 * i]     = __floats2half2_rn(v.x, v.y);
        reinterpret_cast<__half2*>(dst)[2 * i + 1] = __floats2half2_rn(v.z, v.w);
    }
}

// Batched f2h over the four weight matrices (all 768*6144 = 4.7M elements)
__global__ __launch_bounds__(256)
void f2h_w4(const float* __restrict__ s0, const float* __restrict__ s1,
            const float* __restrict__ s2, const float* __restrict__ s3,
            __half* __restrict__ dst, int n4, long dstride)
{
    const int z = blockIdx.z;
    const float* src = (z == 0) ? s0 : (z == 1) ? s1 : (z == 2) ? s2 : s3;
    dst += (long)z * dstride;
    int i = blockIdx.x * 256 + threadIdx.x;
    if (i < n4) {
        float4 v = reinterpret_cast<const float4*>(src)[i];
        reinterpret_cast<__half2*>(dst)[2 * i]     = __floats2half2_rn(v.x, v.y);
        reinterpret_cast<__half2*>(dst)[2 * i + 1] = __floats2half2_rn(v.z, v.w);
    }
}

// Zero rowsum
__global__ __launch_bounds__(256)
void zero_kernel(float* __restrict__ p, int n)
{
    int i = blockIdx.x * 256 + threadIdx.x;
    if (i < n) p[i] = 0.f;
}

// Split-K reduce: out = sum_s psum[s] + bias
__global__ __launch_bounds__(256)
void reduce_kernel(const float* __restrict__ psum, const float* __restrict__ bias,
                   float* __restrict__ out, int n4)
{
    int i = blockIdx.x * 256 + threadIdx.x;
    if (i >= n4) return;
    const int col = (i * 4) % EE;
    float4 b4 = *reinterpret_cast<const float4*>(&bias[col]);
    float4 a = reinterpret_cast<const float4*>(psum)[i];
    float4 b = reinterpret_cast<const float4*>(psum + (size_t)MR * EE)[i];
    float4 c = reinterpret_cast<const float4*>(psum + (size_t)2 * MR * EE)[i];
    float4 o;
    o.x = a.x + b.x + c.x + b4.x;
    o.y = a.y + b.y + c.y + b4.y;
    o.z = a.z + b.z + c.z + b4.z;
    o.w = a.w + b.w + c.w + b4.w;
    reinterpret_cast<float4*>(out)[i] = o;
}

// ---------------------------------------------------------------------------
extern "C" void kernel_launch(void* const* d_in, const int* in_sizes, int n_in,
                              void* d_out, int out_size)
{
    const float* x  = (const float*)d_in[0];   // [4,2048,768]
    const float* Wq = (const float*)d_in[1];   // [768,6144]
    const float* Wk = (const float*)d_in[2];
    const float* Wv = (const float*)d_in[3];
    const float* Wu = (const float*)d_in[4];   // [6144,768]
    const float* bu = (const float*)d_in[5];   // [768]
    float* out = (float*)d_out;                // [8192,768]

    __half *x16, *w16, *qkv, *p16, *ho;
    float *rowsum, *psum;
    cudaGetSymbolAddress((void**)&x16,    g_x16);
    cudaGetSymbolAddress((void**)&w16,    g_w16);
    cudaGetSymbolAddress((void**)&qkv,    g_qkv);
    cudaGetSymbolAddress((void**)&p16,    g_p16);
    cudaGetSymbolAddress((void**)&rowsum, g_rowsum);
    cudaGetSymbolAddress((void**)&ho,     g_ho);
    cudaGetSymbolAddress((void**)&psum,   g_psum);

    __half* q = qkv;
    __half* k = qkv + (size_t)MR * HE;
    __half* v = qkv + (size_t)2 * MR * HE;
    const long WSZ = (long)HE * EE;
    __half* w16u = w16 + 3 * WSZ;              // Wu fp16, native [6144,768]

    cudaFuncSetAttribute(hgemm<0, true >, cudaFuncAttributeMaxDynamicSharedMemorySize, SMEM_TOTAL);
    cudaFuncSetAttribute(hgemm<1, true >, cudaFuncAttributeMaxDynamicSharedMemorySize, SMEM_TOTAL);
    cudaFuncSetAttribute(hgemm<2, false>, cudaFuncAttributeMaxDynamicSharedMemorySize, SMEM_TOTAL);
    cudaFuncSetAttribute(hgemm<3, true >, cudaFuncAttributeMaxDynamicSharedMemorySize, SMEM_TOTAL);

    const dim3 blk(256);
    const dim3 gblk(128);
    const float alpha_exp = 1.4426950408889634f / sqrtf((float)EE);
    const int WN4 = (int)(WSZ / 4);

    // 0: zero rowsum; 1: x -> fp16; 2: weights -> fp16 (native layout, z=4)
    zero_kernel<<<(BB * HH * TT + 255) / 256, blk>>>(rowsum, BB * HH * TT);
    f2h_kernel<<<(MR * EE / 4 + 255) / 256, blk>>>(x, x16, MR * EE / 4);
    f2h_w4<<<dim3((WN4 + 255) / 256, 1, 4), blk>>>(Wq, Wk, Wv, Wu, w16, WN4, WSZ);

    // 3: QKV projections (batched z=3), B = W (N-major, trans-load)
    hgemm<0, true><<<dim3(HE/128, MR/128, 3), gblk, SMEM_TOTAL>>>(
        x16, w16, qkv, nullptr,
        EE, EE, HE, HE,
        1, 0, 0, WSZ, 0, (long)MR * HE, 0, 1.f);

    // 4: scores + exp + rowsum (B = k, K-major)
    hgemm<2, false><<<dim3(TT/128, TT/128, BB*HH), gblk, SMEM_TOTAL>>>(
        q, k, p16, rowsum,
        EE, HE, HE, TT,
        HH, (long)TT * HE, (long)EE, (long)TT * HE, (long)EE,
        (long)HH * TT * TT, (long)TT * TT, alpha_exp);

    // 5: O = (p @ v) / rowsum -> ho fp16  (B = v, N-major trans-load)
    hgemm<3, true><<<dim3(EE/128, TT/128, BB*HH), gblk, SMEM_TOTAL>>>(
        p16, v, ho, rowsum,
        TT, TT, HE, HE,
        HH, (long)HH * TT * TT, (long)TT * TT,
        (long)TT * HE, (long)EE,
        (long)TT * HE, (long)EE, 1.f);

    // 6: output projection, split-K=3 (B = Wu, N-major trans-load)
    hgemm<1, true><<<dim3(EE/128, MR/128, NSPLIT), gblk, SMEM_TOTAL>>>(
        ho, w16u, psum, nullptr,
        HE / NSPLIT, HE, EE, EE,
        1, (long)(HE / NSPLIT), 0, (long)(HE / NSPLIT) * EE, 0,
        (long)MR * EE, 0, 1.f);

    // 7: reduce partials + bias -> fp32 out
    reduce_kernel<<<(MR * EE / 4 + 255) / 256, blk>>>(psum, bu, out, MR * EE / 4);
}